// round 2
// baseline (speedup 1.0000x reference)
#include <cuda_runtime.h>
#include <math.h>

#define BB 128
#define TT 512
#define II 512
#define HH 512
#define H3 1536
#define KK 512

// ---------------- scratch (device globals: allocation-free) ----------------
__device__ float g_xlin[(size_t)BB * TT * H3];   // [B,T,3H]  402.7 MB
__device__ float g_wt[KK * H3];                  // Wh transposed: wt[k][n] = Wh[n][k]
__device__ float g_hbuf[2][BB * HH];             // ping-pong hidden state

// ---------------- small helpers ----------------
__global__ void copy_f(const float* __restrict__ src, float* __restrict__ dst, int n) {
    int i = blockIdx.x * blockDim.x + threadIdx.x;
    if (i < n) dst[i] = src[i];
}

// Wh [1536,512] -> wt [512,1536]
__global__ void transpose_wh(const float* __restrict__ wh, float* __restrict__ wt) {
    __shared__ float tile[32][33];
    int kb = blockIdx.x * 32;
    int nb = blockIdx.y * 32;
    int tx = threadIdx.x;
    int ty = threadIdx.y;
#pragma unroll
    for (int i = 0; i < 32; i += 8)
        tile[ty + i][tx] = wh[(size_t)(nb + ty + i) * KK + kb + tx];
    __syncthreads();
#pragma unroll
    for (int i = 0; i < 32; i += 8)
        wt[(size_t)(kb + ty + i) * H3 + nb + tx] = tile[tx][ty + i];
}

// ---------------- Phase 1: x_lin = x @ Wx^T + bx ----------------
__global__ void __launch_bounds__(256, 2) sgemm_xlin(
    const float* __restrict__ A,    // x  [M,K]
    const float* __restrict__ Bw,   // Wx [N,K]
    const float* __restrict__ bias, // bx [N]
    float* __restrict__ C)          // [M,N]
{
    __shared__ float As[16][128];
    __shared__ float Bs[16][128];

    const int tid = threadIdx.x;
    const int m0 = blockIdx.y * 128;
    const int n0 = blockIdx.x * 128;

    const int lrow = tid >> 2;
    const int lkq  = tid & 3;
    const float* Ap = A  + (size_t)(m0 + lrow) * KK + lkq * 4;
    const float* Bp = Bw + (size_t)(n0 + lrow) * KK + lkq * 4;

    const int tn = tid & 15;
    const int tm = tid >> 4;

    float acc[8][8];
#pragma unroll
    for (int i = 0; i < 8; i++)
#pragma unroll
        for (int j = 0; j < 8; j++) acc[i][j] = 0.f;

    float4 ra0, ra1, rb0, rb1;

    auto ldtile = [&](int kt) {
        ra0 = *(const float4*)(Ap + kt * 16);
        ra1 = *(const float4*)(Ap + (size_t)64 * KK + kt * 16);
        rb0 = *(const float4*)(Bp + kt * 16);
        rb1 = *(const float4*)(Bp + (size_t)64 * KK + kt * 16);
    };
    auto sttile = [&]() {
        As[lkq * 4 + 0][lrow] = ra0.x; As[lkq * 4 + 1][lrow] = ra0.y;
        As[lkq * 4 + 2][lrow] = ra0.z; As[lkq * 4 + 3][lrow] = ra0.w;
        As[lkq * 4 + 0][lrow + 64] = ra1.x; As[lkq * 4 + 1][lrow + 64] = ra1.y;
        As[lkq * 4 + 2][lrow + 64] = ra1.z; As[lkq * 4 + 3][lrow + 64] = ra1.w;
        Bs[lkq * 4 + 0][lrow] = rb0.x; Bs[lkq * 4 + 1][lrow] = rb0.y;
        Bs[lkq * 4 + 2][lrow] = rb0.z; Bs[lkq * 4 + 3][lrow] = rb0.w;
        Bs[lkq * 4 + 0][lrow + 64] = rb1.x; Bs[lkq * 4 + 1][lrow + 64] = rb1.y;
        Bs[lkq * 4 + 2][lrow + 64] = rb1.z; Bs[lkq * 4 + 3][lrow + 64] = rb1.w;
    };
    auto compute = [&]() {
#pragma unroll
        for (int k = 0; k < 16; k++) {
            float a[8], b[8];
#pragma unroll
            for (int i = 0; i < 8; i++) a[i] = As[k][tm * 8 + i];
#pragma unroll
            for (int j = 0; j < 8; j++) b[j] = Bs[k][tn * 8 + j];
#pragma unroll
            for (int i = 0; i < 8; i++)
#pragma unroll
                for (int j = 0; j < 8; j++) acc[i][j] = fmaf(a[i], b[j], acc[i][j]);
        }
    };

    ldtile(0);
    sttile();
    __syncthreads();
    const int NT = KK / 16;
    for (int kt = 1; kt < NT; kt++) {
        ldtile(kt);
        compute();
        __syncthreads();
        sttile();
        __syncthreads();
    }
    compute();

    float bv[8];
#pragma unroll
    for (int j = 0; j < 8; j++) bv[j] = bias[n0 + tn * 8 + j];
#pragma unroll
    for (int i = 0; i < 8; i++) {
        size_t row = (size_t)(m0 + tm * 8 + i);
        float4 c0 = make_float4(acc[i][0] + bv[0], acc[i][1] + bv[1],
                                acc[i][2] + bv[2], acc[i][3] + bv[3]);
        float4 c1 = make_float4(acc[i][4] + bv[4], acc[i][5] + bv[5],
                                acc[i][6] + bv[6], acc[i][7] + bv[7]);
        float4* cp = (float4*)(C + row * H3 + n0 + tn * 8);
        cp[0] = c0;
        cp[1] = c1;
    }
}

// ---------------- Phase 2: one GRU timestep (V2) ----------------
// 128 CTAs (16 unit-groups x 8 batch-groups), 256 threads.
// CTA covers 32 units x 16 batches. Thread = (kg in lane bits 0-1) x
// (4 units) x (2 batches): 24 FMAs per k, K split 4 ways across kg,
// reduced with 2 shfl_xor butterflies. h tile in smem with kg-blocked
// padded layout (conflict-free LDS). Gating fused (kg==0 lanes).
#define HB_STRIDE 528   // per-batch smem row: 4 kg-blocks x 132
#define KG_STRIDE 132

__global__ void __launch_bounds__(256, 1) gru_step(
    const float* __restrict__ xlin,  // [B,T,3H]
    const float* __restrict__ wt,    // [K,3H]
    const float* __restrict__ h_in,  // [B,H]
    float* __restrict__ h_out,       // [B,H]
    float* __restrict__ y,           // [B,T,H]
    int t)
{
    __shared__ float hs[16 * HB_STRIDE];   // 33 KB

    const int tid = threadIdx.x;
    const int kg  = tid & 3;          // K-split group (lane bits 0-1)
    const int ot  = tid >> 2;         // output thread 0..63
    const int ut  = ot & 7;           // unit quad 0..7
    const int bt  = ot >> 3;          // batch pair 0..7 (== warp id)
    const int u0  = blockIdx.x * 32 + ut * 4;
    const int b0  = blockIdx.y * 16;

    // ---- load h tile [16][512] -> padded smem, coalesced float4 ----
    {
        const float4* hin4 = (const float4*)(h_in + (size_t)b0 * HH);
#pragma unroll
        for (int j = 0; j < 8; j++) {
            int idx = tid + j * 256;          // 0..2047
            int b   = idx >> 7;               // batch 0..15
            int kq  = idx & 127;              // float4 index in row
            float4 v = hin4[idx];
            *(float4*)(hs + b * HB_STRIDE + (kq >> 5) * KG_STRIDE + ((kq * 4) & 127)) = v;
        }
    }
    __syncthreads();

    // ---- main K/4 loop: 24 FMAs per k ----
    float acc[24];
#pragma unroll
    for (int i = 0; i < 24; i++) acc[i] = 0.f;

    const int bl = bt * 2;                       // local batch base
    const float* h0p = hs + bl * HB_STRIDE + kg * KG_STRIDE;
    const float* h1p = h0p + HB_STRIDE;
    const float* wp  = wt + (size_t)(kg * 128) * H3 + u0;

#pragma unroll 4
    for (int kk = 0; kk < 128; kk++) {
        float4 wz = *(const float4*)(wp);
        float4 wr = *(const float4*)(wp + 512);
        float4 wn = *(const float4*)(wp + 1024);
        float  ha = h0p[kk];
        float  hb = h1p[kk];
        // acc layout: gate*8 + j*2 + e
        acc[0]  = fmaf(wz.x, ha, acc[0]);  acc[1]  = fmaf(wz.x, hb, acc[1]);
        acc[2]  = fmaf(wz.y, ha, acc[2]);  acc[3]  = fmaf(wz.y, hb, acc[3]);
        acc[4]  = fmaf(wz.z, ha, acc[4]);  acc[5]  = fmaf(wz.z, hb, acc[5]);
        acc[6]  = fmaf(wz.w, ha, acc[6]);  acc[7]  = fmaf(wz.w, hb, acc[7]);
        acc[8]  = fmaf(wr.x, ha, acc[8]);  acc[9]  = fmaf(wr.x, hb, acc[9]);
        acc[10] = fmaf(wr.y, ha, acc[10]); acc[11] = fmaf(wr.y, hb, acc[11]);
        acc[12] = fmaf(wr.z, ha, acc[12]); acc[13] = fmaf(wr.z, hb, acc[13]);
        acc[14] = fmaf(wr.w, ha, acc[14]); acc[15] = fmaf(wr.w, hb, acc[15]);
        acc[16] = fmaf(wn.x, ha, acc[16]); acc[17] = fmaf(wn.x, hb, acc[17]);
        acc[18] = fmaf(wn.y, ha, acc[18]); acc[19] = fmaf(wn.y, hb, acc[19]);
        acc[20] = fmaf(wn.z, ha, acc[20]); acc[21] = fmaf(wn.z, hb, acc[21]);
        acc[22] = fmaf(wn.w, ha, acc[22]); acc[23] = fmaf(wn.w, hb, acc[23]);
        wp += H3;
    }

    // ---- butterfly reduction over kg (lane bits 0-1) ----
#pragma unroll
    for (int i = 0; i < 24; i++) {
        acc[i] += __shfl_xor_sync(0xffffffffu, acc[i], 1);
        acc[i] += __shfl_xor_sync(0xffffffffu, acc[i], 2);
    }

    // ---- gating (kg == 0 lanes: 64 threads x 8 outputs) ----
    if (kg == 0) {
#pragma unroll
        for (int e = 0; e < 2; e++) {
            const int b = b0 + bl + e;
            const float* xl = xlin + ((size_t)b * TT + t) * H3;
            float* ho = h_out + (size_t)b * HH;
            float* yo = y + ((size_t)b * TT + t) * HH;
#pragma unroll
            for (int j = 0; j < 4; j++) {
                const int u = u0 + j;
                float az = acc[0  + j * 2 + e];
                float ar = acc[8  + j * 2 + e];
                float an = acc[16 + j * 2 + e];
                float xz = xl[u];
                float xr = xl[u + 512];
                float xn = xl[u + 1024];
                float hold = hs[(bl + e) * HB_STRIDE + (u >> 7) * KG_STRIDE + (u & 127)];
                float z = 1.f / (1.f + __expf(-(xz + az)));
                float r = 1.f / (1.f + __expf(-(xr + ar)));
                float n = tanhf(xn + r * an);
                float hn = fmaf(z, hold - n, n);   // (1-z)*n + z*hold
                ho[u] = hn;
                yo[u] = hn;
            }
        }
    }
}

// ---------------- launch ----------------
extern "C" void kernel_launch(void* const* d_in, const int* in_sizes, int n_in,
                              void* d_out, int out_size) {
    const float* x  = (const float*)d_in[0];  // [B,T,I]
    const float* h0 = (const float*)d_in[1];  // [B,H]
    const float* Wx = (const float*)d_in[2];  // [3H,I]
    const float* bx = (const float*)d_in[3];  // [3H]
    const float* Wh = (const float*)d_in[4];  // [3H,H]
    float* out = (float*)d_out;

    float *xlin, *wt, *hbuf;
    cudaGetSymbolAddress((void**)&xlin, g_xlin);
    cudaGetSymbolAddress((void**)&wt, g_wt);
    cudaGetSymbolAddress((void**)&hbuf, g_hbuf);

    copy_f<<<(BB * HH + 255) / 256, 256>>>(h0, hbuf, BB * HH);
    transpose_wh<<<dim3(KK / 32, H3 / 32), dim3(32, 8)>>>(Wh, wt);

    sgemm_xlin<<<dim3(H3 / 128, (BB * TT) / 128), 256>>>(x, Wx, bx, xlin);

    for (int t = 0; t < TT; t++) {
        const float* hin = hbuf + (size_t)(t & 1) * BB * HH;
        float* hout      = hbuf + (size_t)((t + 1) & 1) * BB * HH;
        gru_step<<<dim3(HH / 32, BB / 16), 256>>>(xlin, wt, hin, hout, out, t);
    }

    if (out_size >= (int)((size_t)BB * TT * HH + BB * HH)) {
        copy_f<<<(BB * HH + 255) / 256, 256>>>(hbuf, out + (size_t)BB * TT * HH,
                                               BB * HH);
    }
}

// round 3
// speedup vs baseline: 1.8269x; 1.8269x over previous
#include <cuda_runtime.h>
#include <math.h>

#define BB 128
#define TT 512
#define II 512
#define HH 512
#define H3 1536
#define KK 512
#define NCTA 128

// ---------------- scratch (device globals: allocation-free) ----------------
__device__ float g_xlin[(size_t)BB * TT * H3];   // [B,T,3H]
__device__ float g_wt[KK * H3];                  // Wh transposed: wt[k][n] = Wh[n][k]
__device__ float g_hbuf[2][BB * HH];             // ping-pong hidden state
__device__ int g_bar_count;
__device__ volatile int g_bar_flag;

// ---------------- small helpers ----------------
__global__ void copy_f(const float* __restrict__ src, float* __restrict__ dst, int n) {
    int i = blockIdx.x * blockDim.x + threadIdx.x;
    if (i < n) dst[i] = src[i];
}

__global__ void reset_bar() { g_bar_count = 0; g_bar_flag = 0; }

// Wh [1536,512] -> wt [512,1536]
__global__ void transpose_wh(const float* __restrict__ wh, float* __restrict__ wt) {
    __shared__ float tile[32][33];
    int kb = blockIdx.x * 32;
    int nb = blockIdx.y * 32;
    int tx = threadIdx.x;
    int ty = threadIdx.y;
#pragma unroll
    for (int i = 0; i < 32; i += 8)
        tile[ty + i][tx] = wh[(size_t)(nb + ty + i) * KK + kb + tx];
    __syncthreads();
#pragma unroll
    for (int i = 0; i < 32; i += 8)
        wt[(size_t)(kb + ty + i) * H3 + nb + tx] = tile[tx][ty + i];
}

// ---------------- Phase 1: x_lin = x @ Wx^T + bx ----------------
__global__ void __launch_bounds__(256, 2) sgemm_xlin(
    const float* __restrict__ A,    // x  [M,K]
    const float* __restrict__ Bw,   // Wx [N,K]
    const float* __restrict__ bias, // bx [N]
    float* __restrict__ C)          // [M,N]
{
    __shared__ float As[16][128];
    __shared__ float Bs[16][128];

    const int tid = threadIdx.x;
    const int m0 = blockIdx.y * 128;
    const int n0 = blockIdx.x * 128;

    const int lrow = tid >> 2;
    const int lkq  = tid & 3;
    const float* Ap = A  + (size_t)(m0 + lrow) * KK + lkq * 4;
    const float* Bp = Bw + (size_t)(n0 + lrow) * KK + lkq * 4;

    const int tn = tid & 15;
    const int tm = tid >> 4;

    float acc[8][8];
#pragma unroll
    for (int i = 0; i < 8; i++)
#pragma unroll
        for (int j = 0; j < 8; j++) acc[i][j] = 0.f;

    float4 ra0, ra1, rb0, rb1;

    auto ldtile = [&](int kt) {
        ra0 = *(const float4*)(Ap + kt * 16);
        ra1 = *(const float4*)(Ap + (size_t)64 * KK + kt * 16);
        rb0 = *(const float4*)(Bp + kt * 16);
        rb1 = *(const float4*)(Bp + (size_t)64 * KK + kt * 16);
    };
    auto sttile = [&]() {
        As[lkq * 4 + 0][lrow] = ra0.x; As[lkq * 4 + 1][lrow] = ra0.y;
        As[lkq * 4 + 2][lrow] = ra0.z; As[lkq * 4 + 3][lrow] = ra0.w;
        As[lkq * 4 + 0][lrow + 64] = ra1.x; As[lkq * 4 + 1][lrow + 64] = ra1.y;
        As[lkq * 4 + 2][lrow + 64] = ra1.z; As[lkq * 4 + 3][lrow + 64] = ra1.w;
        Bs[lkq * 4 + 0][lrow] = rb0.x; Bs[lkq * 4 + 1][lrow] = rb0.y;
        Bs[lkq * 4 + 2][lrow] = rb0.z; Bs[lkq * 4 + 3][lrow] = rb0.w;
        Bs[lkq * 4 + 0][lrow + 64] = rb1.x; Bs[lkq * 4 + 1][lrow + 64] = rb1.y;
        Bs[lkq * 4 + 2][lrow + 64] = rb1.z; Bs[lkq * 4 + 3][lrow + 64] = rb1.w;
    };
    auto compute = [&]() {
#pragma unroll
        for (int k = 0; k < 16; k++) {
            float a[8], b[8];
#pragma unroll
            for (int i = 0; i < 8; i++) a[i] = As[k][tm * 8 + i];
#pragma unroll
            for (int j = 0; j < 8; j++) b[j] = Bs[k][tn * 8 + j];
#pragma unroll
            for (int i = 0; i < 8; i++)
#pragma unroll
                for (int j = 0; j < 8; j++) acc[i][j] = fmaf(a[i], b[j], acc[i][j]);
        }
    };

    ldtile(0);
    sttile();
    __syncthreads();
    const int NT = KK / 16;
    for (int kt = 1; kt < NT; kt++) {
        ldtile(kt);
        compute();
        __syncthreads();
        sttile();
        __syncthreads();
    }
    compute();

    float bv[8];
#pragma unroll
    for (int j = 0; j < 8; j++) bv[j] = bias[n0 + tn * 8 + j];
#pragma unroll
    for (int i = 0; i < 8; i++) {
        size_t row = (size_t)(m0 + tm * 8 + i);
        float4 c0 = make_float4(acc[i][0] + bv[0], acc[i][1] + bv[1],
                                acc[i][2] + bv[2], acc[i][3] + bv[3]);
        float4 c1 = make_float4(acc[i][4] + bv[4], acc[i][5] + bv[5],
                                acc[i][6] + bv[6], acc[i][7] + bv[7]);
        float4* cp = (float4*)(C + row * H3 + n0 + tn * 8);
        cp[0] = c0;
        cp[1] = c1;
    }
}

// ---------------- grid-wide barrier (all NCTA CTAs resident in wave 1) -----
__device__ __forceinline__ void grid_barrier(int phase) {
    __syncthreads();
    if (threadIdx.x == 0) {
        __threadfence();
        int v = atomicAdd(&g_bar_count, 1);
        if (v == NCTA - 1) {
            g_bar_count = 0;
            __threadfence();
            g_bar_flag = phase;        // release
        } else {
            while (g_bar_flag < phase) { }  // volatile spin
            __threadfence();           // acquire
        }
    }
    __syncthreads();
}

// ---------------- Phase 2: persistent GRU recurrence ----------------
// 128 CTAs x 256 threads, one launch for all T steps.
// CTA = (ug: 32 units, bg: 16 batches). Warp: lane = unit within group.
// wid = (kh<<2)|bq : kh = K-half (256 k), bq = batch quad (4 batches).
// Thread: 1 unit x 4 batches x 3 gates over its K-half -> 12 accumulators.
// Weights read via coalesced LDG.32 -> stay L1-resident across steps
// (no launch boundary = no L1D flush). Cross-kh reduce via smem, gating
// fused, one grid barrier per step.
__global__ void __launch_bounds__(256, 1) gru_persist(
    const float* __restrict__ xlin,  // [B,T,3H]
    const float* __restrict__ wt,    // [K,3H]
    float* __restrict__ hbuf,        // g_hbuf base (2 x BB*HH)
    float* __restrict__ y)           // [B,T,H]
{
    __shared__ float hs[16][512];        // 32 KB batch-slice of h
    __shared__ float red[4][32][13];     // 6.5 KB kh=1 partials (padded)

    const int tid  = threadIdx.x;
    const int lane = tid & 31;
    const int wid  = tid >> 5;
    const int kh   = wid >> 2;           // 0,1
    const int bq   = wid & 3;            // 0..3
    const int ug   = blockIdx.x & 15;
    const int bg   = blockIdx.x >> 4;
    const int u    = ug * 32 + lane;
    const int b0   = bg * 16;
    const int k0   = kh * 256;

    for (int t = 0; t < TT; t++) {
        const float* hin = hbuf + (size_t)(t & 1) * (BB * HH);
        float* hout      = hbuf + (size_t)((t + 1) & 1) * (BB * HH);

        // ---- stage h tile [16][512], coalesced float4 ----
        {
            const float4* hin4 = (const float4*)(hin + (size_t)b0 * HH);
            float4* hs4 = (float4*)hs;
#pragma unroll
            for (int j = 0; j < 8; j++) hs4[tid + j * 256] = hin4[tid + j * 256];
        }
        __syncthreads();

        // ---- prefetch gating operands (hide DRAM latency under the dots) --
        float pxz[4], pxr[4], pxn[4];
        if (kh == 0) {
#pragma unroll
            for (int j = 0; j < 4; j++) {
                const int b = b0 + bq * 4 + j;
                const float* xl = xlin + ((size_t)b * TT + t) * H3;
                pxz[j] = __ldg(xl + u);
                pxr[j] = __ldg(xl + u + 512);
                pxn[j] = __ldg(xl + u + 1024);
            }
        }

        // ---- dot products over this thread's K-half ----
        float acc[12];
#pragma unroll
        for (int i = 0; i < 12; i++) acc[i] = 0.f;

        const float* wp = wt + (size_t)k0 * H3 + u;
        const int bl0 = bq * 4;

        for (int kk = 0; kk < 256; kk += 4) {
            float4 ha = *(const float4*)&hs[bl0 + 0][k0 + kk];
            float4 hb = *(const float4*)&hs[bl0 + 1][k0 + kk];
            float4 hc = *(const float4*)&hs[bl0 + 2][k0 + kk];
            float4 hd = *(const float4*)&hs[bl0 + 3][k0 + kk];
            const float* ap = (const float*)&ha;
            const float* bp = (const float*)&hb;
            const float* cp = (const float*)&hc;
            const float* dp = (const float*)&hd;
#pragma unroll
            for (int q = 0; q < 4; q++) {
                const float* wq = wp + (size_t)q * H3;
                float wz = wq[0];
                float wr = wq[512];
                float wn = wq[1024];
                float h0 = ap[q], h1 = bp[q], h2 = cp[q], h3 = dp[q];
                acc[0]  = fmaf(wz, h0, acc[0]);
                acc[1]  = fmaf(wr, h0, acc[1]);
                acc[2]  = fmaf(wn, h0, acc[2]);
                acc[3]  = fmaf(wz, h1, acc[3]);
                acc[4]  = fmaf(wr, h1, acc[4]);
                acc[5]  = fmaf(wn, h1, acc[5]);
                acc[6]  = fmaf(wz, h2, acc[6]);
                acc[7]  = fmaf(wr, h2, acc[7]);
                acc[8]  = fmaf(wn, h2, acc[8]);
                acc[9]  = fmaf(wz, h3, acc[9]);
                acc[10] = fmaf(wr, h3, acc[10]);
                acc[11] = fmaf(wn, h3, acc[11]);
            }
            wp += 4 * H3;
        }

        // ---- cross-kh reduce + gating ----
        if (kh == 1) {
#pragma unroll
            for (int i = 0; i < 12; i++) red[bq][lane][i] = acc[i];
        }
        __syncthreads();
        if (kh == 0) {
#pragma unroll
            for (int i = 0; i < 12; i++) acc[i] += red[bq][lane][i];
#pragma unroll
            for (int j = 0; j < 4; j++) {
                const int bl = bl0 + j;
                const int b  = b0 + bl;
                float az = acc[j * 3 + 0];
                float ar = acc[j * 3 + 1];
                float an = acc[j * 3 + 2];
                float hold = hs[bl][u];
                float z = 1.f / (1.f + __expf(-(pxz[j] + az)));
                float r = 1.f / (1.f + __expf(-(pxr[j] + ar)));
                float n = tanhf(pxn[j] + r * an);
                float hn = fmaf(z, hold - n, n);   // (1-z)*n + z*hold
                hout[(size_t)b * HH + u] = hn;
                y[((size_t)b * TT + t) * HH + u] = hn;
            }
        }

        grid_barrier(t + 1);
    }
}

// ---------------- launch ----------------
extern "C" void kernel_launch(void* const* d_in, const int* in_sizes, int n_in,
                              void* d_out, int out_size) {
    const float* x  = (const float*)d_in[0];  // [B,T,I]
    const float* h0 = (const float*)d_in[1];  // [B,H]
    const float* Wx = (const float*)d_in[2];  // [3H,I]
    const float* bx = (const float*)d_in[3];  // [3H]
    const float* Wh = (const float*)d_in[4];  // [3H,H]
    float* out = (float*)d_out;

    float *xlin, *wt, *hbuf;
    cudaGetSymbolAddress((void**)&xlin, g_xlin);
    cudaGetSymbolAddress((void**)&wt, g_wt);
    cudaGetSymbolAddress((void**)&hbuf, g_hbuf);

    reset_bar<<<1, 1>>>();
    copy_f<<<(BB * HH + 255) / 256, 256>>>(h0, hbuf, BB * HH);
    transpose_wh<<<dim3(KK / 32, H3 / 32), dim3(32, 8)>>>(Wh, wt);

    // phase 1: input projections for all timesteps
    sgemm_xlin<<<dim3(H3 / 128, (BB * TT) / 128), 256>>>(x, Wx, bx, xlin);

    // phase 2: persistent recurrence, single launch
    gru_persist<<<NCTA, 256>>>(xlin, wt, hbuf, out);

    // h_final (T even -> final state in buffer 0)
    if (out_size >= (int)((size_t)BB * TT * HH + BB * HH)) {
        copy_f<<<(BB * HH + 255) / 256, 256>>>(hbuf, out + (size_t)BB * TT * HH,
                                               BB * HH);
    }
}

// round 5
// speedup vs baseline: 2.0566x; 1.1257x over previous
#include <cuda_runtime.h>
#include <cuda_bf16.h>
#include <math.h>
#include <cstdint>

#define BB 128
#define TT 512
#define II 512
#define HH 512
#define H3 1536
#define KK 512
#define NCTA 128

// ---------------- scratch (device globals: allocation-free) ----------------
__device__ float g_xlin[(size_t)BB * TT * H3];            // [B,T,3H]
__device__ float g_wt[KK * H3];                           // Wh^T
__device__ float g_hbuf[2][BB * HH];                      // ping-pong h
__device__ __nv_bfloat16 g_xhi[(size_t)BB * TT * II];     // x hi
__device__ __nv_bfloat16 g_xlo[(size_t)BB * TT * II];     // x lo
__device__ __nv_bfloat16 g_wxhi[H3 * II];                 // Wx hi
__device__ __nv_bfloat16 g_wxlo[H3 * II];                 // Wx lo
__device__ int g_bar_count;
__device__ volatile int g_bar_flag;

// ================= PTX helpers (baseline ISA only: sm_80+) =================
#define CP_ASYNC16(dst, src) \
    asm volatile("cp.async.cg.shared.global [%0], [%1], 16;" \
                 :: "r"(dst), "l"(src) : "memory")
#define CP_COMMIT() asm volatile("cp.async.commit_group;" ::: "memory")
template <int N>
__device__ __forceinline__ void cp_wait() {
    asm volatile("cp.async.wait_group %0;" :: "n"(N) : "memory");
}

__device__ __forceinline__ uint32_t smem_to_u32(const void* p) {
    uint32_t a;
    asm("{ .reg .u64 t; cvta.to.shared.u64 t, %1; cvt.u32.u64 %0, t; }"
        : "=r"(a) : "l"(p));
    return a;
}

__device__ __forceinline__ void ldmatrix_x4(uint32_t& r0, uint32_t& r1,
                                            uint32_t& r2, uint32_t& r3,
                                            uint32_t addr) {
    asm volatile("ldmatrix.sync.aligned.m8n8.x4.shared.b16 {%0,%1,%2,%3}, [%4];"
                 : "=r"(r0), "=r"(r1), "=r"(r2), "=r"(r3) : "r"(addr));
}

__device__ __forceinline__ void mma_bf16(float* c, const uint32_t* a,
                                         const uint32_t* b) {
    asm volatile(
        "mma.sync.aligned.m16n8k16.row.col.f32.bf16.bf16.f32 "
        "{%0,%1,%2,%3}, {%4,%5,%6,%7}, {%8,%9}, {%0,%1,%2,%3};"
        : "+f"(c[0]), "+f"(c[1]), "+f"(c[2]), "+f"(c[3])
        : "r"(a[0]), "r"(a[1]), "r"(a[2]), "r"(a[3]), "r"(b[0]), "r"(b[1]));
}

// ---------------- small helpers ----------------
__global__ void copy_f(const float* __restrict__ src, float* __restrict__ dst, int n) {
    int i = blockIdx.x * blockDim.x + threadIdx.x;
    if (i < n) dst[i] = src[i];
}
__global__ void reset_bar() { g_bar_count = 0; g_bar_flag = 0; }

// fp32 -> bf16 hi/lo split (2 elems per thread)
__global__ void split_bf16(const float* __restrict__ src,
                           __nv_bfloat16* __restrict__ hi,
                           __nv_bfloat16* __restrict__ lo, int n2) {
    int i = blockIdx.x * blockDim.x + threadIdx.x;
    if (i >= n2) return;
    float2 v = ((const float2*)src)[i];
    __nv_bfloat16 h0 = __float2bfloat16(v.x);
    __nv_bfloat16 h1 = __float2bfloat16(v.y);
    float r0 = v.x - __bfloat162float(h0);
    float r1 = v.y - __bfloat162float(h1);
    ((__nv_bfloat162*)hi)[i] = __nv_bfloat162(h0, h1);
    ((__nv_bfloat162*)lo)[i] = __nv_bfloat162(__float2bfloat16(r0), __float2bfloat16(r1));
}

// Wh [1536,512] -> wt [512,1536]
__global__ void transpose_wh(const float* __restrict__ wh, float* __restrict__ wt) {
    __shared__ float tile[32][33];
    int kb = blockIdx.x * 32;
    int nb = blockIdx.y * 32;
    int tx = threadIdx.x;
    int ty = threadIdx.y;
#pragma unroll
    for (int i = 0; i < 32; i += 8)
        tile[ty + i][tx] = wh[(size_t)(nb + ty + i) * KK + kb + tx];
    __syncthreads();
#pragma unroll
    for (int i = 0; i < 32; i += 8)
        wt[(size_t)(kb + ty + i) * H3 + nb + tx] = tile[tx][ty + i];
}

// ---------------- Phase 1: bf16-split GEMM via mma.sync ----------------
// C = Ahi*Bhi^T + Ahi*Blo^T + Alo*Bhi^T + bias.
// CTA 128x128, 8 warps (2x4), warp tile 64x32, BK=32, cp.async double buffer.
#define SA 40                       // smem row stride in bf16 (80 B)
#define TILE_B (128 * SA * 2)       // 10240 B per component tile
#define BUF_B (4 * TILE_B)          // 40960 B per buffer (AH, AL, BH, BL)
#define OFF_AH 0
#define OFF_AL TILE_B
#define OFF_BH (2 * TILE_B)
#define OFF_BL (3 * TILE_B)

__global__ void __launch_bounds__(256, 1) gemm_xlin_mma(
    const __nv_bfloat16* __restrict__ Ahi, const __nv_bfloat16* __restrict__ Alo,
    const __nv_bfloat16* __restrict__ Bhi, const __nv_bfloat16* __restrict__ Blo,
    const float* __restrict__ bias, float* __restrict__ C) {
    extern __shared__ char smem[];
    const uint32_t sb = smem_to_u32(smem);

    const int tid = threadIdx.x;
    const int wid = tid >> 5;
    const int lane = tid & 31;
    const int wrow = wid >> 2;          // 0..1  (64 m each)
    const int wcol = wid & 3;           // 0..3  (32 n each)
    const int n0 = blockIdx.x * 128;
    const int m0 = blockIdx.y * 128;

    const __nv_bfloat16* gsrc[4] = {
        Ahi + (size_t)m0 * KK, Alo + (size_t)m0 * KK,
        Bhi + (size_t)n0 * KK, Blo + (size_t)n0 * KK};

    // stage one BK=32 chunk into buffer `buf` with cp.async (8 x 16B / thread)
    auto stage = [&](int kc, int buf) {
        const uint32_t dbase = sb + buf * BUF_B;
        const int row = tid >> 1;               // 0..127
        const int g2 = (tid & 1) * 2;           // 16B-group base {0, 2}
#pragma unroll
        for (int comp = 0; comp < 4; comp++) {
            const __nv_bfloat16* s = gsrc[comp] + (size_t)row * KK + kc * 32;
            uint32_t d = dbase + comp * TILE_B + row * (SA * 2);
            CP_ASYNC16(d + g2 * 16, (const void*)(s + g2 * 8));
            CP_ASYNC16(d + (g2 + 1) * 16, (const void*)(s + (g2 + 1) * 8));
        }
        CP_COMMIT();
    };

    float acc[4][4][4];
#pragma unroll
    for (int i = 0; i < 4; i++)
#pragma unroll
        for (int j = 0; j < 4; j++)
#pragma unroll
            for (int q = 0; q < 4; q++) acc[i][j][q] = 0.f;

    // ldmatrix address pieces: row = base + lane%16, col = ks*16 + (lane/16)*8
    const int lrow = lane & 15;
    const int lcol8 = (lane >> 4) * 8;

    stage(0, 0);

    const int NCHUNK = KK / 32;  // 16
    for (int kc = 0; kc < NCHUNK; kc++) {
        const int buf = kc & 1;
        if (kc + 1 < NCHUNK) {
            stage(kc + 1, buf ^ 1);
            cp_wait<1>();
        } else {
            cp_wait<0>();
        }
        __syncthreads();

        const uint32_t bb = sb + buf * BUF_B;
#pragma unroll
        for (int ks = 0; ks < 2; ks++) {
            const uint32_t coloff = (ks * 16 + lcol8) * 2;
            // B fragments: 4 n-tiles x {hi,lo} x 2 regs
            uint32_t bh[4][2], bl[4][2];
#pragma unroll
            for (int half = 0; half < 2; half++) {
                const uint32_t brow = (wcol * 32 + half * 16 + lrow) * (SA * 2);
                uint32_t r0, r1, r2, r3;
                ldmatrix_x4(r0, r1, r2, r3, bb + OFF_BH + brow + coloff);
                bh[half * 2 + 0][0] = r0; bh[half * 2 + 1][0] = r1;
                bh[half * 2 + 0][1] = r2; bh[half * 2 + 1][1] = r3;
                ldmatrix_x4(r0, r1, r2, r3, bb + OFF_BL + brow + coloff);
                bl[half * 2 + 0][0] = r0; bl[half * 2 + 1][0] = r1;
                bl[half * 2 + 0][1] = r2; bl[half * 2 + 1][1] = r3;
            }
#pragma unroll
            for (int mt = 0; mt < 4; mt++) {
                const uint32_t arow = (wrow * 64 + mt * 16 + lrow) * (SA * 2);
                uint32_t ah[4], al[4];
                ldmatrix_x4(ah[0], ah[1], ah[2], ah[3], bb + OFF_AH + arow + coloff);
                ldmatrix_x4(al[0], al[1], al[2], al[3], bb + OFF_AL + arow + coloff);
#pragma unroll
                for (int nt = 0; nt < 4; nt++) {
                    mma_bf16(acc[mt][nt], ah, bh[nt]);
                    mma_bf16(acc[mt][nt], ah, bl[nt]);
                    mma_bf16(acc[mt][nt], al, bh[nt]);
                }
            }
        }
        __syncthreads();
    }

    // epilogue: D fragment (c0,c1)@(row, col..col+1), (c2,c3)@(row+8)
    const int erow = m0 + wrow * 64 + (lane >> 2);
    const int ecol0 = n0 + wcol * 32 + (lane & 3) * 2;
#pragma unroll
    for (int mt = 0; mt < 4; mt++) {
#pragma unroll
        for (int nt = 0; nt < 4; nt++) {
            const int col = ecol0 + nt * 8;
            const float b0 = bias[col], b1 = bias[col + 1];
            const int r0 = erow + mt * 16;
            float2 v0 = make_float2(acc[mt][nt][0] + b0, acc[mt][nt][1] + b1);
            float2 v1 = make_float2(acc[mt][nt][2] + b0, acc[mt][nt][3] + b1);
            *(float2*)(C + (size_t)r0 * H3 + col) = v0;
            *(float2*)(C + (size_t)(r0 + 8) * H3 + col) = v1;
        }
    }
}

// ---------------- grid-wide barrier ----------------
__device__ __forceinline__ void grid_barrier(int phase) {
    __syncthreads();
    if (threadIdx.x == 0) {
        __threadfence();
        int v = atomicAdd(&g_bar_count, 1);
        if (v == NCTA - 1) {
            g_bar_count = 0;
            __threadfence();
            g_bar_flag = phase;
        } else {
            while (g_bar_flag < phase) { }
            __threadfence();
        }
    }
    __syncthreads();
}

// ---------------- Phase 2: persistent GRU recurrence ----------------
__global__ void __launch_bounds__(256, 1) gru_persist(
    const float* __restrict__ xlin,  // [B,T,3H]
    const float* __restrict__ wt,    // [K,3H]
    float* __restrict__ hbuf,        // 2 x BB*HH
    float* __restrict__ y)           // [B,T,H]
{
    __shared__ float hs[16][512];
    __shared__ float red[4][32][13];

    const int tid  = threadIdx.x;
    const int lane = tid & 31;
    const int wid  = tid >> 5;
    const int kh   = wid >> 2;
    const int bq   = wid & 3;
    const int ug   = blockIdx.x & 15;
    const int bg   = blockIdx.x >> 4;
    const int u    = ug * 32 + lane;
    const int b0   = bg * 16;
    const int k0   = kh * 256;

    for (int t = 0; t < TT; t++) {
        const float* hin = hbuf + (size_t)(t & 1) * (BB * HH);
        float* hout      = hbuf + (size_t)((t + 1) & 1) * (BB * HH);

        {
            const float4* hin4 = (const float4*)(hin + (size_t)b0 * HH);
            float4* hs4 = (float4*)hs;
#pragma unroll
            for (int j = 0; j < 8; j++) hs4[tid + j * 256] = hin4[tid + j * 256];
        }
        __syncthreads();

        float pxz[4], pxr[4], pxn[4];
        if (kh == 0) {
#pragma unroll
            for (int j = 0; j < 4; j++) {
                const int b = b0 + bq * 4 + j;
                const float* xl = xlin + ((size_t)b * TT + t) * H3;
                pxz[j] = __ldg(xl + u);
                pxr[j] = __ldg(xl + u + 512);
                pxn[j] = __ldg(xl + u + 1024);
            }
        }

        float acc[12];
#pragma unroll
        for (int i = 0; i < 12; i++) acc[i] = 0.f;

        const float* wp = wt + (size_t)k0 * H3 + u;
        const int bl0 = bq * 4;

        for (int kk = 0; kk < 256; kk += 4) {
            float4 ha = *(const float4*)&hs[bl0 + 0][k0 + kk];
            float4 hb = *(const float4*)&hs[bl0 + 1][k0 + kk];
            float4 hc = *(const float4*)&hs[bl0 + 2][k0 + kk];
            float4 hd = *(const float4*)&hs[bl0 + 3][k0 + kk];
            const float* ap = (const float*)&ha;
            const float* bp = (const float*)&hb;
            const float* cp = (const float*)&hc;
            const float* dp = (const float*)&hd;
#pragma unroll
            for (int q = 0; q < 4; q++) {
                const float* wq = wp + (size_t)q * H3;
                float wz = wq[0];
                float wr = wq[512];
                float wn = wq[1024];
                float h0 = ap[q], h1 = bp[q], h2 = cp[q], h3 = dp[q];
                acc[0]  = fmaf(wz, h0, acc[0]);
                acc[1]  = fmaf(wr, h0, acc[1]);
                acc[2]  = fmaf(wn, h0, acc[2]);
                acc[3]  = fmaf(wz, h1, acc[3]);
                acc[4]  = fmaf(wr, h1, acc[4]);
                acc[5]  = fmaf(wn, h1, acc[5]);
                acc[6]  = fmaf(wz, h2, acc[6]);
                acc[7]  = fmaf(wr, h2, acc[7]);
                acc[8]  = fmaf(wn, h2, acc[8]);
                acc[9]  = fmaf(wz, h3, acc[9]);
                acc[10] = fmaf(wr, h3, acc[10]);
                acc[11] = fmaf(wn, h3, acc[11]);
            }
            wp += 4 * H3;
        }

        if (kh == 1) {
#pragma unroll
            for (int i = 0; i < 12; i++) red[bq][lane][i] = acc[i];
        }
        __syncthreads();
        if (kh == 0) {
#pragma unroll
            for (int i = 0; i < 12; i++) acc[i] += red[bq][lane][i];
#pragma unroll
            for (int j = 0; j < 4; j++) {
                const int bl = bl0 + j;
                const int b  = b0 + bl;
                float az = acc[j * 3 + 0];
                float ar = acc[j * 3 + 1];
                float an = acc[j * 3 + 2];
                float hold = hs[bl][u];
                float z = 1.f / (1.f + __expf(-(pxz[j] + az)));
                float r = 1.f / (1.f + __expf(-(pxr[j] + ar)));
                float n = tanhf(pxn[j] + r * an);
                float hn = fmaf(z, hold - n, n);
                hout[(size_t)b * HH + u] = hn;
                y[((size_t)b * TT + t) * HH + u] = hn;
            }
        }

        grid_barrier(t + 1);
    }
}

// ---------------- launch ----------------
extern "C" void kernel_launch(void* const* d_in, const int* in_sizes, int n_in,
                              void* d_out, int out_size) {
    const float* x  = (const float*)d_in[0];  // [B,T,I]
    const float* h0 = (const float*)d_in[1];  // [B,H]
    const float* Wx = (const float*)d_in[2];  // [3H,I]
    const float* bx = (const float*)d_in[3];  // [3H]
    const float* Wh = (const float*)d_in[4];  // [3H,H]
    float* out = (float*)d_out;

    float *xlin, *wt, *hbuf;
    __nv_bfloat16 *xhi, *xlo, *wxhi, *wxlo;
    cudaGetSymbolAddress((void**)&xlin, g_xlin);
    cudaGetSymbolAddress((void**)&wt, g_wt);
    cudaGetSymbolAddress((void**)&hbuf, g_hbuf);
    cudaGetSymbolAddress((void**)&xhi, g_xhi);
    cudaGetSymbolAddress((void**)&xlo, g_xlo);
    cudaGetSymbolAddress((void**)&wxhi, g_wxhi);
    cudaGetSymbolAddress((void**)&wxlo, g_wxlo);

    cudaFuncSetAttribute(gemm_xlin_mma, cudaFuncAttributeMaxDynamicSharedMemorySize,
                         2 * BUF_B);

    reset_bar<<<1, 1>>>();
    copy_f<<<(BB * HH + 255) / 256, 256>>>(h0, hbuf, BB * HH);
    transpose_wh<<<dim3(KK / 32, H3 / 32), dim3(32, 8)>>>(Wh, wt);

    // bf16 hi/lo splits
    {
        int n2x = (BB * TT * II) / 2;
        split_bf16<<<(n2x + 255) / 256, 256>>>(x, xhi, xlo, n2x);
        int n2w = (H3 * II) / 2;
        split_bf16<<<(n2w + 255) / 256, 256>>>(Wx, wxhi, wxlo, n2w);
    }

    // phase 1: tensor-core (HMMA) input projections
    gemm_xlin_mma<<<dim3(H3 / 128, (BB * TT) / 128), 256, 2 * BUF_B>>>(
        xhi, xlo, wxhi, wxlo, bx, xlin);

    // phase 2: persistent recurrence
    gru_persist<<<NCTA, 256>>>(xlin, wt, hbuf, out);

    // h_final
    if (out_size >= (int)((size_t)BB * TT * HH + BB * HH)) {
        copy_f<<<(BB * HH + 255) / 256, 256>>>(hbuf, out + (size_t)BB * TT * HH,
                                               BB * HH);
    }
}

// round 6
// speedup vs baseline: 2.6693x; 1.2979x over previous
#include <cuda_runtime.h>
#include <cuda_bf16.h>
#include <math.h>
#include <cstdint>

#define BB 128
#define TT 512
#define II 512
#define HH 512
#define H3 1536
#define KK 512
#define NCTA 128

// ---------------- scratch (device globals: allocation-free) ----------------
__device__ float g_xlin[(size_t)BB * TT * H3];            // [B,T,3H]
__device__ float g_h[BB * HH];                            // h fp32
__device__ __nv_bfloat16 g_hhi[BB * HH];                  // h hi
__device__ __nv_bfloat16 g_hlo[BB * HH];                  // h lo
__device__ __nv_bfloat16 g_xhi[(size_t)BB * TT * II];     // x hi
__device__ __nv_bfloat16 g_xlo[(size_t)BB * TT * II];     // x lo
__device__ __nv_bfloat16 g_wxhi[H3 * II];                 // Wx hi
__device__ __nv_bfloat16 g_wxlo[H3 * II];                 // Wx lo
__device__ __nv_bfloat16 g_whhi[H3 * HH];                 // Wh hi  [N=1536][K=512]
__device__ __nv_bfloat16 g_whlo[H3 * HH];                 // Wh lo
__device__ float g_part[(size_t)8 * BB * H3];             // K-split partials 6.3MB
__device__ int g_bar_count;
__device__ volatile int g_bar_flag;

// ================= PTX helpers (baseline ISA only: sm_80+) =================
#define CP_ASYNC16(dst, src) \
    asm volatile("cp.async.cg.shared.global [%0], [%1], 16;" \
                 :: "r"(dst), "l"(src) : "memory")
#define CP_COMMIT() asm volatile("cp.async.commit_group;" ::: "memory")
template <int N>
__device__ __forceinline__ void cp_wait() {
    asm volatile("cp.async.wait_group %0;" :: "n"(N) : "memory");
}

__device__ __forceinline__ uint32_t smem_to_u32(const void* p) {
    uint32_t a;
    asm("{ .reg .u64 t; cvta.to.shared.u64 t, %1; cvt.u32.u64 %0, t; }"
        : "=r"(a) : "l"(p));
    return a;
}

__device__ __forceinline__ void ldmatrix_x4(uint32_t& r0, uint32_t& r1,
                                            uint32_t& r2, uint32_t& r3,
                                            uint32_t addr) {
    asm volatile("ldmatrix.sync.aligned.m8n8.x4.shared.b16 {%0,%1,%2,%3}, [%4];"
                 : "=r"(r0), "=r"(r1), "=r"(r2), "=r"(r3) : "r"(addr));
}

__device__ __forceinline__ void mma_bf16(float* c, const uint32_t* a,
                                         const uint32_t* b) {
    asm volatile(
        "mma.sync.aligned.m16n8k16.row.col.f32.bf16.bf16.f32 "
        "{%0,%1,%2,%3}, {%4,%5,%6,%7}, {%8,%9}, {%0,%1,%2,%3};"
        : "+f"(c[0]), "+f"(c[1]), "+f"(c[2]), "+f"(c[3])
        : "r"(a[0]), "r"(a[1]), "r"(a[2]), "r"(a[3]), "r"(b[0]), "r"(b[1]));
}

// ---------------- small helpers ----------------
__global__ void copy_f(const float* __restrict__ src, float* __restrict__ dst, int n) {
    int i = blockIdx.x * blockDim.x + threadIdx.x;
    if (i < n) dst[i] = src[i];
}
__global__ void reset_bar() { g_bar_count = 0; g_bar_flag = 0; }

// fp32 -> bf16 hi/lo split (2 elems per thread)
__global__ void split_bf16(const float* __restrict__ src,
                           __nv_bfloat16* __restrict__ hi,
                           __nv_bfloat16* __restrict__ lo, int n2) {
    int i = blockIdx.x * blockDim.x + threadIdx.x;
    if (i >= n2) return;
    float2 v = ((const float2*)src)[i];
    __nv_bfloat16 h0 = __float2bfloat16(v.x);
    __nv_bfloat16 h1 = __float2bfloat16(v.y);
    float r0 = v.x - __bfloat162float(h0);
    float r1 = v.y - __bfloat162float(h1);
    ((__nv_bfloat162*)hi)[i] = __nv_bfloat162(h0, h1);
    ((__nv_bfloat162*)lo)[i] = __nv_bfloat162(__float2bfloat16(r0), __float2bfloat16(r1));
}

// h0 -> fp32 copy + bf16 hi/lo split
__global__ void split_h0(const float* __restrict__ h0, float* __restrict__ h,
                         __nv_bfloat16* __restrict__ hhi,
                         __nv_bfloat16* __restrict__ hlo, int n) {
    int i = blockIdx.x * blockDim.x + threadIdx.x;
    if (i >= n) return;
    float v = h0[i];
    __nv_bfloat16 hb = __float2bfloat16(v);
    h[i] = v;
    hhi[i] = hb;
    hlo[i] = __float2bfloat16(v - __bfloat162float(hb));
}

// ---------------- Phase 1: bf16-split GEMM via mma.sync (proven) ----------
#define SA 40
#define TILE_B (128 * SA * 2)
#define BUF_B (4 * TILE_B)
#define OFF_AH 0
#define OFF_AL TILE_B
#define OFF_BH (2 * TILE_B)
#define OFF_BL (3 * TILE_B)

__global__ void __launch_bounds__(256, 1) gemm_xlin_mma(
    const __nv_bfloat16* __restrict__ Ahi, const __nv_bfloat16* __restrict__ Alo,
    const __nv_bfloat16* __restrict__ Bhi, const __nv_bfloat16* __restrict__ Blo,
    const float* __restrict__ bias, float* __restrict__ C) {
    extern __shared__ char smem[];
    const uint32_t sb = smem_to_u32(smem);

    const int tid = threadIdx.x;
    const int wid = tid >> 5;
    const int lane = tid & 31;
    const int wrow = wid >> 2;
    const int wcol = wid & 3;
    const int n0 = blockIdx.x * 128;
    const int m0 = blockIdx.y * 128;

    const __nv_bfloat16* gsrc[4] = {
        Ahi + (size_t)m0 * KK, Alo + (size_t)m0 * KK,
        Bhi + (size_t)n0 * KK, Blo + (size_t)n0 * KK};

    auto stage = [&](int kc, int buf) {
        const uint32_t dbase = sb + buf * BUF_B;
        const int row = tid >> 1;
        const int g2 = (tid & 1) * 2;
#pragma unroll
        for (int comp = 0; comp < 4; comp++) {
            const __nv_bfloat16* s = gsrc[comp] + (size_t)row * KK + kc * 32;
            uint32_t d = dbase + comp * TILE_B + row * (SA * 2);
            CP_ASYNC16(d + g2 * 16, (const void*)(s + g2 * 8));
            CP_ASYNC16(d + (g2 + 1) * 16, (const void*)(s + (g2 + 1) * 8));
        }
        CP_COMMIT();
    };

    float acc[4][4][4];
#pragma unroll
    for (int i = 0; i < 4; i++)
#pragma unroll
        for (int j = 0; j < 4; j++)
#pragma unroll
            for (int q = 0; q < 4; q++) acc[i][j][q] = 0.f;

    const int lrow = lane & 15;
    const int lcol8 = (lane >> 4) * 8;

    stage(0, 0);

    const int NCHUNK = KK / 32;
    for (int kc = 0; kc < NCHUNK; kc++) {
        const int buf = kc & 1;
        if (kc + 1 < NCHUNK) {
            stage(kc + 1, buf ^ 1);
            cp_wait<1>();
        } else {
            cp_wait<0>();
        }
        __syncthreads();

        const uint32_t bb = sb + buf * BUF_B;
#pragma unroll
        for (int ks = 0; ks < 2; ks++) {
            const uint32_t coloff = (ks * 16 + lcol8) * 2;
            uint32_t bh[4][2], bl[4][2];
#pragma unroll
            for (int half = 0; half < 2; half++) {
                const uint32_t brow = (wcol * 32 + half * 16 + lrow) * (SA * 2);
                uint32_t r0, r1, r2, r3;
                ldmatrix_x4(r0, r1, r2, r3, bb + OFF_BH + brow + coloff);
                bh[half * 2 + 0][0] = r0; bh[half * 2 + 1][0] = r1;
                bh[half * 2 + 0][1] = r2; bh[half * 2 + 1][1] = r3;
                ldmatrix_x4(r0, r1, r2, r3, bb + OFF_BL + brow + coloff);
                bl[half * 2 + 0][0] = r0; bl[half * 2 + 1][0] = r1;
                bl[half * 2 + 0][1] = r2; bl[half * 2 + 1][1] = r3;
            }
#pragma unroll
            for (int mt = 0; mt < 4; mt++) {
                const uint32_t arow = (wrow * 64 + mt * 16 + lrow) * (SA * 2);
                uint32_t ah[4], al[4];
                ldmatrix_x4(ah[0], ah[1], ah[2], ah[3], bb + OFF_AH + arow + coloff);
                ldmatrix_x4(al[0], al[1], al[2], al[3], bb + OFF_AL + arow + coloff);
#pragma unroll
                for (int nt = 0; nt < 4; nt++) {
                    mma_bf16(acc[mt][nt], ah, bh[nt]);
                    mma_bf16(acc[mt][nt], ah, bl[nt]);
                    mma_bf16(acc[mt][nt], al, bh[nt]);
                }
            }
        }
        __syncthreads();
    }

    const int erow = m0 + wrow * 64 + (lane >> 2);
    const int ecol0 = n0 + wcol * 32 + (lane & 3) * 2;
#pragma unroll
    for (int mt = 0; mt < 4; mt++) {
#pragma unroll
        for (int nt = 0; nt < 4; nt++) {
            const int col = ecol0 + nt * 8;
            const float b0 = bias[col], b1 = bias[col + 1];
            const int r0 = erow + mt * 16;
            float2 v0 = make_float2(acc[mt][nt][0] + b0, acc[mt][nt][1] + b1);
            float2 v1 = make_float2(acc[mt][nt][2] + b0, acc[mt][nt][3] + b1);
            *(float2*)(C + (size_t)r0 * H3 + col) = v0;
            *(float2*)(C + (size_t)(r0 + 8) * H3 + col) = v1;
        }
    }
}

// ---------------- grid-wide barrier ----------------
__device__ __forceinline__ void grid_barrier(int phase) {
    __syncthreads();
    if (threadIdx.x == 0) {
        __threadfence();
        int v = atomicAdd(&g_bar_count, 1);
        if (v == NCTA - 1) {
            g_bar_count = 0;
            __threadfence();
            g_bar_flag = phase;
        } else {
            while (g_bar_flag < phase) { }
            __threadfence();
        }
    }
    __syncthreads();
}

// ---------------- Phase 2: persistent HMMA recurrence ----------------
// 128 CTAs x 256 threads. Per step:
//   Phase A (CTA<96, = nt(0..11) x ks(0..7)): partial[128b x 128n] =
//     h_split[128 x 64k] @ WhT_split via 3-pass bf16 mma. Wh tiles resident
//     in smem for all steps; h tile re-staged per step via cp.async.cg.
//   Phase B (all CTAs, CTA = batch): reduce 8 partials (__ldcg), gate,
//     write h fp32 + bf16 hi/lo split + y.
#define SA2 72                      // 144B row stride (16B-aligned, LDSM ok)
#define T2 (128 * SA2)              // halves per tile

__global__ void __launch_bounds__(256, 1) gru_persist_mma(
    const float* __restrict__ xlin,
    const __nv_bfloat16* __restrict__ whhi,
    const __nv_bfloat16* __restrict__ whlo,
    float* __restrict__ h,
    __nv_bfloat16* __restrict__ hhi,
    __nv_bfloat16* __restrict__ hlo,
    float* __restrict__ part,
    float* __restrict__ y) {
    extern __shared__ __nv_bfloat16 sm2[];  // 4*T2 halves = 73728 B
    const uint32_t sb = smem_to_u32(sm2);

    const int tid = threadIdx.x;
    const int lane = tid & 31;
    const int wid = tid >> 5;
    const int wrow = wid >> 2;          // 0..1
    const int wcol = wid & 3;           // 0..3
    const int cta = blockIdx.x;
    const bool act = cta < 96;
    const int nt = cta >> 3;            // 0..11
    const int ks = cta & 7;             // 0..7
    const int lrow = lane & 15;
    const int lcol8 = (lane >> 4) * 8;

    // ---- stage persistent Wh tiles (hi at 2*T2, lo at 3*T2) ----
    if (act) {
        const int row = tid >> 1;       // n-local 0..127
        const int seg = tid & 1;        // 64B half of the 128B row
        const __nv_bfloat16* s0 = whhi + (size_t)(nt * 128 + row) * KK + ks * 64 + seg * 32;
        const __nv_bfloat16* s1 = whlo + (size_t)(nt * 128 + row) * KK + ks * 64 + seg * 32;
        uint32_t d0 = sb + (uint32_t)(2 * T2 + row * SA2 + seg * 32) * 2;
        uint32_t d1 = sb + (uint32_t)(3 * T2 + row * SA2 + seg * 32) * 2;
#pragma unroll
        for (int j = 0; j < 4; j++) {
            CP_ASYNC16(d0 + j * 16, (const void*)(s0 + j * 8));
            CP_ASYNC16(d1 + j * 16, (const void*)(s1 + j * 8));
        }
        CP_COMMIT();
        cp_wait<0>();
    }
    __syncthreads();

    for (int t = 0; t < TT; t++) {
        grid_barrier(2 * t + 1);        // h splits from prev step visible

        if (act) {
            // ---- stage A = h splits [128 b x 64 k] (hi at 0, lo at T2) ----
            const int row = tid >> 1;
            const int seg = tid & 1;
            const __nv_bfloat16* s0 = hhi + row * HH + ks * 64 + seg * 32;
            const __nv_bfloat16* s1 = hlo + row * HH + ks * 64 + seg * 32;
            uint32_t d0 = sb + (uint32_t)(row * SA2 + seg * 32) * 2;
            uint32_t d1 = sb + (uint32_t)(T2 + row * SA2 + seg * 32) * 2;
#pragma unroll
            for (int j = 0; j < 4; j++) {
                CP_ASYNC16(d0 + j * 16, (const void*)(s0 + j * 8));
                CP_ASYNC16(d1 + j * 16, (const void*)(s1 + j * 8));
            }
            CP_COMMIT();
            cp_wait<0>();
            __syncthreads();

            float acc[4][4][4];
#pragma unroll
            for (int i = 0; i < 4; i++)
#pragma unroll
                for (int j = 0; j < 4; j++)
#pragma unroll
                    for (int q = 0; q < 4; q++) acc[i][j][q] = 0.f;

#pragma unroll
            for (int k16 = 0; k16 < 4; k16++) {
                const uint32_t coloff = (k16 * 16 + lcol8) * 2;
                uint32_t bh[4][2], bl[4][2];
#pragma unroll
                for (int half = 0; half < 2; half++) {
                    const uint32_t brow = (wcol * 32 + half * 16 + lrow) * (SA2 * 2);
                    uint32_t r0, r1, r2, r3;
                    ldmatrix_x4(r0, r1, r2, r3, sb + 2 * T2 * 2 + brow + coloff);
                    bh[half * 2 + 0][0] = r0; bh[half * 2 + 1][0] = r1;
                    bh[half * 2 + 0][1] = r2; bh[half * 2 + 1][1] = r3;
                    ldmatrix_x4(r0, r1, r2, r3, sb + 3 * T2 * 2 + brow + coloff);
                    bl[half * 2 + 0][0] = r0; bl[half * 2 + 1][0] = r1;
                    bl[half * 2 + 0][1] = r2; bl[half * 2 + 1][1] = r3;
                }
#pragma unroll
                for (int mt = 0; mt < 4; mt++) {
                    const uint32_t arow = (wrow * 64 + mt * 16 + lrow) * (SA2 * 2);
                    uint32_t ah[4], al[4];
                    ldmatrix_x4(ah[0], ah[1], ah[2], ah[3], sb + arow + coloff);
                    ldmatrix_x4(al[0], al[1], al[2], al[3], sb + T2 * 2 + arow + coloff);
#pragma unroll
                    for (int ntt = 0; ntt < 4; ntt++) {
                        mma_bf16(acc[mt][ntt], ah, bh[ntt]);
                        mma_bf16(acc[mt][ntt], ah, bl[ntt]);
                        mma_bf16(acc[mt][ntt], al, bh[ntt]);
                    }
                }
            }

            // ---- epilogue: partials to gmem [ks][128][1536] ----
            const int erow = wrow * 64 + (lane >> 2);
            const int ecol0 = nt * 128 + wcol * 32 + (lane & 3) * 2;
#pragma unroll
            for (int mt = 0; mt < 4; mt++) {
#pragma unroll
                for (int ntt = 0; ntt < 4; ntt++) {
                    const int col = ecol0 + ntt * 8;
                    const int r0 = erow + mt * 16;
                    *(float2*)(part + ((size_t)ks * BB + r0) * H3 + col) =
                        make_float2(acc[mt][ntt][0], acc[mt][ntt][1]);
                    *(float2*)(part + ((size_t)ks * BB + r0 + 8) * H3 + col) =
                        make_float2(acc[mt][ntt][2], acc[mt][ntt][3]);
                }
            }
            __threadfence();
            __syncthreads();   // smem A reuse safety for next step
        }

        grid_barrier(2 * t + 2);        // partials visible

        // ---- phase B: CTA = batch, 2 units per thread ----
#pragma unroll
        for (int uu = 0; uu < 2; uu++) {
            const int u = tid + uu * 256;
            float az = 0.f, ar = 0.f, an = 0.f;
#pragma unroll
            for (int q = 0; q < 8; q++) {
                const float* pp = part + ((size_t)q * BB + cta) * H3 + u;
                az += __ldcg(pp);
                ar += __ldcg(pp + 512);
                an += __ldcg(pp + 1024);
            }
            const float* xl = xlin + ((size_t)cta * TT + t) * H3;
            float xz = xl[u];
            float xr = xl[u + 512];
            float xn = xl[u + 1024];
            float hold = h[cta * HH + u];
            float z = 1.f / (1.f + __expf(-(xz + az)));
            float r = 1.f / (1.f + __expf(-(xr + ar)));
            float n = tanhf(xn + r * an);
            float hn = fmaf(z, hold - n, n);
            h[cta * HH + u] = hn;
            y[((size_t)cta * TT + t) * HH + u] = hn;
            __nv_bfloat16 hb = __float2bfloat16(hn);
            hhi[cta * HH + u] = hb;
            hlo[cta * HH + u] = __float2bfloat16(hn - __bfloat162float(hb));
        }
        __threadfence();
    }
}

// ---------------- launch ----------------
extern "C" void kernel_launch(void* const* d_in, const int* in_sizes, int n_in,
                              void* d_out, int out_size) {
    const float* x  = (const float*)d_in[0];  // [B,T,I]
    const float* h0 = (const float*)d_in[1];  // [B,H]
    const float* Wx = (const float*)d_in[2];  // [3H,I]
    const float* bx = (const float*)d_in[3];  // [3H]
    const float* Wh = (const float*)d_in[4];  // [3H,H]
    float* out = (float*)d_out;

    float *xlin, *h, *part;
    __nv_bfloat16 *xhi, *xlo, *wxhi, *wxlo, *whhi, *whlo, *hhi, *hlo;
    cudaGetSymbolAddress((void**)&xlin, g_xlin);
    cudaGetSymbolAddress((void**)&h, g_h);
    cudaGetSymbolAddress((void**)&part, g_part);
    cudaGetSymbolAddress((void**)&xhi, g_xhi);
    cudaGetSymbolAddress((void**)&xlo, g_xlo);
    cudaGetSymbolAddress((void**)&wxhi, g_wxhi);
    cudaGetSymbolAddress((void**)&wxlo, g_wxlo);
    cudaGetSymbolAddress((void**)&whhi, g_whhi);
    cudaGetSymbolAddress((void**)&whlo, g_whlo);
    cudaGetSymbolAddress((void**)&hhi, g_hhi);
    cudaGetSymbolAddress((void**)&hlo, g_hlo);

    cudaFuncSetAttribute(gemm_xlin_mma, cudaFuncAttributeMaxDynamicSharedMemorySize,
                         2 * BUF_B);
    cudaFuncSetAttribute(gru_persist_mma, cudaFuncAttributeMaxDynamicSharedMemorySize,
                         4 * T2 * 2);

    reset_bar<<<1, 1>>>();
    split_h0<<<(BB * HH + 255) / 256, 256>>>(h0, h, hhi, hlo, BB * HH);

    // bf16 hi/lo splits for x, Wx, Wh
    {
        int n2x = (BB * TT * II) / 2;
        split_bf16<<<(n2x + 255) / 256, 256>>>(x, xhi, xlo, n2x);
        int n2w = (H3 * II) / 2;
        split_bf16<<<(n2w + 255) / 256, 256>>>(Wx, wxhi, wxlo, n2w);
        int n2h = (H3 * HH) / 2;
        split_bf16<<<(n2h + 255) / 256, 256>>>(Wh, whhi, whlo, n2h);
    }

    // phase 1: tensor-core (HMMA) input projections
    gemm_xlin_mma<<<dim3(H3 / 128, (BB * TT) / 128), 256, 2 * BUF_B>>>(
        xhi, xlo, wxhi, wxlo, bx, xlin);

    // phase 2: persistent HMMA recurrence
    gru_persist_mma<<<NCTA, 256, 4 * T2 * 2>>>(xlin, whhi, whlo, h, hhi, hlo,
                                               part, out);

    // h_final
    if (out_size >= (int)((size_t)BB * TT * HH + BB * HH)) {
        copy_f<<<(BB * HH + 255) / 256, 256>>>(h, out + (size_t)BB * TT * HH,
                                               BB * HH);
    }
}

// round 7
// speedup vs baseline: 2.9344x; 1.0993x over previous
#include <cuda_runtime.h>
#include <cuda_bf16.h>
#include <math.h>
#include <cstdint>

#define BB 128
#define TT 512
#define II 512
#define HH 512
#define H3 1536
#define KK 512
#define NCTA 128

// ---------------- scratch (device globals: allocation-free) ----------------
__device__ float g_xlin[(size_t)BB * TT * H3];            // [B,T,3H]
__device__ __nv_bfloat16 g_hhi[BB * HH];                  // h hi
__device__ __nv_bfloat16 g_hlo[BB * HH];                  // h lo
__device__ __nv_bfloat16 g_xhi[(size_t)BB * TT * II];     // x hi
__device__ __nv_bfloat16 g_xlo[(size_t)BB * TT * II];     // x lo
__device__ __nv_bfloat16 g_wxhi[H3 * II];                 // Wx hi
__device__ __nv_bfloat16 g_wxlo[H3 * II];                 // Wx lo
__device__ __nv_bfloat16 g_whhi[H3 * HH];                 // Wh hi  [N=1536][K=512]
__device__ __nv_bfloat16 g_whlo[H3 * HH];                 // Wh lo
__device__ float g_part[(size_t)8 * BB * H3];             // K-split partials 6.3MB
__device__ int g_bar_count;

// ================= PTX helpers (baseline ISA only: sm_80+) =================
#define CP_ASYNC16(dst, src) \
    asm volatile("cp.async.cg.shared.global [%0], [%1], 16;" \
                 :: "r"(dst), "l"(src) : "memory")
#define CP_COMMIT() asm volatile("cp.async.commit_group;" ::: "memory")
template <int N>
__device__ __forceinline__ void cp_wait() {
    asm volatile("cp.async.wait_group %0;" :: "n"(N) : "memory");
}

__device__ __forceinline__ uint32_t smem_to_u32(const void* p) {
    uint32_t a;
    asm("{ .reg .u64 t; cvta.to.shared.u64 t, %1; cvt.u32.u64 %0, t; }"
        : "=r"(a) : "l"(p));
    return a;
}

__device__ __forceinline__ void ldmatrix_x4(uint32_t& r0, uint32_t& r1,
                                            uint32_t& r2, uint32_t& r3,
                                            uint32_t addr) {
    asm volatile("ldmatrix.sync.aligned.m8n8.x4.shared.b16 {%0,%1,%2,%3}, [%4];"
                 : "=r"(r0), "=r"(r1), "=r"(r2), "=r"(r3) : "r"(addr));
}

__device__ __forceinline__ void mma_bf16(float* c, const uint32_t* a,
                                         const uint32_t* b) {
    asm volatile(
        "mma.sync.aligned.m16n8k16.row.col.f32.bf16.bf16.f32 "
        "{%0,%1,%2,%3}, {%4,%5,%6,%7}, {%8,%9}, {%0,%1,%2,%3};"
        : "+f"(c[0]), "+f"(c[1]), "+f"(c[2]), "+f"(c[3])
        : "r"(a[0]), "r"(a[1]), "r"(a[2]), "r"(a[3]), "r"(b[0]), "r"(b[1]));
}

// ---------------- small helpers ----------------
__global__ void reset_bar() { g_bar_count = 0; }

// h_final gather: dst[b*H+u] = y[b, T-1, u]
__global__ void copy_hfinal(const float* __restrict__ y, float* __restrict__ dst,
                            int n) {
    int i = blockIdx.x * blockDim.x + threadIdx.x;
    if (i >= n) return;
    int b = i >> 9;
    int u = i & 511;
    dst[i] = y[((size_t)b * TT + (TT - 1)) * HH + u];
}

// fp32 -> bf16 hi/lo split (2 elems per thread)
__global__ void split_bf16(const float* __restrict__ src,
                           __nv_bfloat16* __restrict__ hi,
                           __nv_bfloat16* __restrict__ lo, int n2) {
    int i = blockIdx.x * blockDim.x + threadIdx.x;
    if (i >= n2) return;
    float2 v = ((const float2*)src)[i];
    __nv_bfloat16 h0 = __float2bfloat16(v.x);
    __nv_bfloat16 h1 = __float2bfloat16(v.y);
    float r0 = v.x - __bfloat162float(h0);
    float r1 = v.y - __bfloat162float(h1);
    ((__nv_bfloat162*)hi)[i] = __nv_bfloat162(h0, h1);
    ((__nv_bfloat162*)lo)[i] = __nv_bfloat162(__float2bfloat16(r0), __float2bfloat16(r1));
}

// h0 -> bf16 hi/lo split
__global__ void split_h0(const float* __restrict__ h0,
                         __nv_bfloat16* __restrict__ hhi,
                         __nv_bfloat16* __restrict__ hlo, int n) {
    int i = blockIdx.x * blockDim.x + threadIdx.x;
    if (i >= n) return;
    float v = h0[i];
    __nv_bfloat16 hb = __float2bfloat16(v);
    hhi[i] = hb;
    hlo[i] = __float2bfloat16(v - __bfloat162float(hb));
}

// ---------------- Phase 1: bf16-split GEMM via mma.sync ----------
#define SA 40
#define TILE_B (128 * SA * 2)
#define BUF_B (4 * TILE_B)
#define OFF_AH 0
#define OFF_AL TILE_B
#define OFF_BH (2 * TILE_B)
#define OFF_BL (3 * TILE_B)

__global__ void __launch_bounds__(256, 2) gemm_xlin_mma(
    const __nv_bfloat16* __restrict__ Ahi, const __nv_bfloat16* __restrict__ Alo,
    const __nv_bfloat16* __restrict__ Bhi, const __nv_bfloat16* __restrict__ Blo,
    const float* __restrict__ bias, float* __restrict__ C) {
    extern __shared__ char smem[];
    const uint32_t sb = smem_to_u32(smem);

    const int tid = threadIdx.x;
    const int wid = tid >> 5;
    const int lane = tid & 31;
    const int wrow = wid >> 2;
    const int wcol = wid & 3;
    const int n0 = blockIdx.x * 128;
    const int m0 = blockIdx.y * 128;

    const __nv_bfloat16* gsrc[4] = {
        Ahi + (size_t)m0 * KK, Alo + (size_t)m0 * KK,
        Bhi + (size_t)n0 * KK, Blo + (size_t)n0 * KK};

    auto stage = [&](int kc, int buf) {
        const uint32_t dbase = sb + buf * BUF_B;
        const int row = tid >> 1;
        const int g2 = (tid & 1) * 2;
#pragma unroll
        for (int comp = 0; comp < 4; comp++) {
            const __nv_bfloat16* s = gsrc[comp] + (size_t)row * KK + kc * 32;
            uint32_t d = dbase + comp * TILE_B + row * (SA * 2);
            CP_ASYNC16(d + g2 * 16, (const void*)(s + g2 * 8));
            CP_ASYNC16(d + (g2 + 1) * 16, (const void*)(s + (g2 + 1) * 8));
        }
        CP_COMMIT();
    };

    float acc[4][4][4];
#pragma unroll
    for (int i = 0; i < 4; i++)
#pragma unroll
        for (int j = 0; j < 4; j++)
#pragma unroll
            for (int q = 0; q < 4; q++) acc[i][j][q] = 0.f;

    const int lrow = lane & 15;
    const int lcol8 = (lane >> 4) * 8;

    stage(0, 0);

    const int NCHUNK = KK / 32;
    for (int kc = 0; kc < NCHUNK; kc++) {
        const int buf = kc & 1;
        if (kc + 1 < NCHUNK) {
            stage(kc + 1, buf ^ 1);
            cp_wait<1>();
        } else {
            cp_wait<0>();
        }
        __syncthreads();

        const uint32_t bb = sb + buf * BUF_B;
#pragma unroll
        for (int ks = 0; ks < 2; ks++) {
            const uint32_t coloff = (ks * 16 + lcol8) * 2;
            uint32_t bh[4][2], bl[4][2];
#pragma unroll
            for (int half = 0; half < 2; half++) {
                const uint32_t brow = (wcol * 32 + half * 16 + lrow) * (SA * 2);
                uint32_t r0, r1, r2, r3;
                ldmatrix_x4(r0, r1, r2, r3, bb + OFF_BH + brow + coloff);
                bh[half * 2 + 0][0] = r0; bh[half * 2 + 1][0] = r1;
                bh[half * 2 + 0][1] = r2; bh[half * 2 + 1][1] = r3;
                ldmatrix_x4(r0, r1, r2, r3, bb + OFF_BL + brow + coloff);
                bl[half * 2 + 0][0] = r0; bl[half * 2 + 1][0] = r1;
                bl[half * 2 + 0][1] = r2; bl[half * 2 + 1][1] = r3;
            }
#pragma unroll
            for (int mt = 0; mt < 4; mt++) {
                const uint32_t arow = (wrow * 64 + mt * 16 + lrow) * (SA * 2);
                uint32_t ah[4], al[4];
                ldmatrix_x4(ah[0], ah[1], ah[2], ah[3], bb + OFF_AH + arow + coloff);
                ldmatrix_x4(al[0], al[1], al[2], al[3], bb + OFF_AL + arow + coloff);
#pragma unroll
                for (int nt = 0; nt < 4; nt++) {
                    mma_bf16(acc[mt][nt], ah, bh[nt]);
                    mma_bf16(acc[mt][nt], ah, bl[nt]);
                    mma_bf16(acc[mt][nt], al, bh[nt]);
                }
            }
        }
        __syncthreads();
    }

    const int erow = m0 + wrow * 64 + (lane >> 2);
    const int ecol0 = n0 + wcol * 32 + (lane & 3) * 2;
#pragma unroll
    for (int mt = 0; mt < 4; mt++) {
#pragma unroll
        for (int nt = 0; nt < 4; nt++) {
            const int col = ecol0 + nt * 8;
            const float b0 = bias[col], b1 = bias[col + 1];
            const int r0 = erow + mt * 16;
            float2 v0 = make_float2(acc[mt][nt][0] + b0, acc[mt][nt][1] + b1);
            float2 v1 = make_float2(acc[mt][nt][2] + b0, acc[mt][nt][3] + b1);
            *(float2*)(C + (size_t)r0 * H3 + col) = v0;
            *(float2*)(C + (size_t)(r0 + 8) * H3 + col) = v1;
        }
    }
}

// ---------------- grid-wide barrier: monotonic RED + poll ----------------
__device__ __forceinline__ void grid_barrier(int phase) {
    __syncthreads();
    if (threadIdx.x == 0) {
        __threadfence();
        atomicAdd(&g_bar_count, 1);            // return unused -> RED
        const int target = NCTA * phase;
        while (*((volatile int*)&g_bar_count) < target) { }
        __threadfence();
    }
    __syncthreads();
}

// ---------------- Phase 2: persistent HMMA recurrence ----------------
// 128 CTAs x 256 threads. Per step:
//   prefetch xlin gate operands (hidden under phase A)
//   Phase A (CTA<96 = nt(0..11) x ks(0..7)): partial = h_split @ WhT_split
//     (3-pass bf16 mma; Wh tiles smem-resident all steps)
//   barrier; Phase B (CTA = batch): reduce partials, gate with reg-carried
//     h_old, write y + h bf16 hi/lo; barrier.
#define SA2 72
#define T2 (128 * SA2)

__global__ void __launch_bounds__(256, 1) gru_persist_mma(
    const float* __restrict__ xlin,
    const __nv_bfloat16* __restrict__ whhi,
    const __nv_bfloat16* __restrict__ whlo,
    const float* __restrict__ h0,
    __nv_bfloat16* __restrict__ hhi,
    __nv_bfloat16* __restrict__ hlo,
    float* __restrict__ part,
    float* __restrict__ y) {
    extern __shared__ __nv_bfloat16 sm2[];
    const uint32_t sb = smem_to_u32(sm2);

    const int tid = threadIdx.x;
    const int lane = tid & 31;
    const int wid = tid >> 5;
    const int wrow = wid >> 2;
    const int wcol = wid & 3;
    const int cta = blockIdx.x;
    const bool act = cta < 96;
    const int nt = cta >> 3;
    const int ks = cta & 7;
    const int lrow = lane & 15;
    const int lcol8 = (lane >> 4) * 8;

    // reg-carried h state for phase B (this thread owns (batch=cta, u, u+256))
    float hold[2];
    hold[0] = h0[cta * HH + tid];
    hold[1] = h0[cta * HH + tid + 256];

    // ---- stage persistent Wh tiles (hi at 2*T2, lo at 3*T2) ----
    if (act) {
        const int row = tid >> 1;
        const int seg = tid & 1;
        const __nv_bfloat16* s0 = whhi + (size_t)(nt * 128 + row) * KK + ks * 64 + seg * 32;
        const __nv_bfloat16* s1 = whlo + (size_t)(nt * 128 + row) * KK + ks * 64 + seg * 32;
        uint32_t d0 = sb + (uint32_t)(2 * T2 + row * SA2 + seg * 32) * 2;
        uint32_t d1 = sb + (uint32_t)(3 * T2 + row * SA2 + seg * 32) * 2;
#pragma unroll
        for (int j = 0; j < 4; j++) {
            CP_ASYNC16(d0 + j * 16, (const void*)(s0 + j * 8));
            CP_ASYNC16(d1 + j * 16, (const void*)(s1 + j * 8));
        }
        CP_COMMIT();
        cp_wait<0>();
    }
    __syncthreads();

    for (int t = 0; t < TT; t++) {
        grid_barrier(2 * t + 1);        // h splits from prev step visible

        // ---- prefetch phase-B gate operands (hide under phase A) ----
        float pxz[2], pxr[2], pxn[2];
        {
            const float* xl = xlin + ((size_t)cta * TT + t) * H3;
#pragma unroll
            for (int uu = 0; uu < 2; uu++) {
                const int u = tid + uu * 256;
                pxz[uu] = xl[u];
                pxr[uu] = xl[u + 512];
                pxn[uu] = xl[u + 1024];
            }
        }

        if (act) {
            // ---- stage A = h splits [128 b x 64 k] (hi at 0, lo at T2) ----
            const int row = tid >> 1;
            const int seg = tid & 1;
            const __nv_bfloat16* s0 = hhi + row * HH + ks * 64 + seg * 32;
            const __nv_bfloat16* s1 = hlo + row * HH + ks * 64 + seg * 32;
            uint32_t d0 = sb + (uint32_t)(row * SA2 + seg * 32) * 2;
            uint32_t d1 = sb + (uint32_t)(T2 + row * SA2 + seg * 32) * 2;
#pragma unroll
            for (int j = 0; j < 4; j++) {
                CP_ASYNC16(d0 + j * 16, (const void*)(s0 + j * 8));
                CP_ASYNC16(d1 + j * 16, (const void*)(s1 + j * 8));
            }
            CP_COMMIT();
            cp_wait<0>();
            __syncthreads();

            float acc[4][4][4];
#pragma unroll
            for (int i = 0; i < 4; i++)
#pragma unroll
                for (int j = 0; j < 4; j++)
#pragma unroll
                    for (int q = 0; q < 4; q++) acc[i][j][q] = 0.f;

#pragma unroll
            for (int k16 = 0; k16 < 4; k16++) {
                const uint32_t coloff = (k16 * 16 + lcol8) * 2;
                uint32_t bh[4][2], bl[4][2];
#pragma unroll
                for (int half = 0; half < 2; half++) {
                    const uint32_t brow = (wcol * 32 + half * 16 + lrow) * (SA2 * 2);
                    uint32_t r0, r1, r2, r3;
                    ldmatrix_x4(r0, r1, r2, r3, sb + 2 * T2 * 2 + brow + coloff);
                    bh[half * 2 + 0][0] = r0; bh[half * 2 + 1][0] = r1;
                    bh[half * 2 + 0][1] = r2; bh[half * 2 + 1][1] = r3;
                    ldmatrix_x4(r0, r1, r2, r3, sb + 3 * T2 * 2 + brow + coloff);
                    bl[half * 2 + 0][0] = r0; bl[half * 2 + 1][0] = r1;
                    bl[half * 2 + 0][1] = r2; bl[half * 2 + 1][1] = r3;
                }
#pragma unroll
                for (int mt = 0; mt < 4; mt++) {
                    const uint32_t arow = (wrow * 64 + mt * 16 + lrow) * (SA2 * 2);
                    uint32_t ah[4], al[4];
                    ldmatrix_x4(ah[0], ah[1], ah[2], ah[3], sb + arow + coloff);
                    ldmatrix_x4(al[0], al[1], al[2], al[3], sb + T2 * 2 + arow + coloff);
#pragma unroll
                    for (int ntt = 0; ntt < 4; ntt++) {
                        mma_bf16(acc[mt][ntt], ah, bh[ntt]);
                        mma_bf16(acc[mt][ntt], ah, bl[ntt]);
                        mma_bf16(acc[mt][ntt], al, bh[ntt]);
                    }
                }
            }

            // ---- epilogue: partials to gmem [ks][128][1536] ----
            const int erow = wrow * 64 + (lane >> 2);
            const int ecol0 = nt * 128 + wcol * 32 + (lane & 3) * 2;
#pragma unroll
            for (int mt = 0; mt < 4; mt++) {
#pragma unroll
                for (int ntt = 0; ntt < 4; ntt++) {
                    const int col = ecol0 + ntt * 8;
                    const int r0 = erow + mt * 16;
                    *(float2*)(part + ((size_t)ks * BB + r0) * H3 + col) =
                        make_float2(acc[mt][ntt][0], acc[mt][ntt][1]);
                    *(float2*)(part + ((size_t)ks * BB + r0 + 8) * H3 + col) =
                        make_float2(acc[mt][ntt][2], acc[mt][ntt][3]);
                }
            }
            __threadfence();
            __syncthreads();   // smem A reuse safety for next step
        }

        grid_barrier(2 * t + 2);        // partials visible

        // ---- phase B: CTA = batch, 2 units per thread ----
#pragma unroll
        for (int uu = 0; uu < 2; uu++) {
            const int u = tid + uu * 256;
            float az = 0.f, ar = 0.f, an = 0.f;
#pragma unroll
            for (int q = 0; q < 8; q++) {
                const float* pp = part + ((size_t)q * BB + cta) * H3 + u;
                az += __ldcg(pp);
                ar += __ldcg(pp + 512);
                an += __ldcg(pp + 1024);
            }
            float z = 1.f / (1.f + __expf(-(pxz[uu] + az)));
            float r = 1.f / (1.f + __expf(-(pxr[uu] + ar)));
            float n = tanhf(pxn[uu] + r * an);
            float hn = fmaf(z, hold[uu] - n, n);
            hold[uu] = hn;
            y[((size_t)cta * TT + t) * HH + u] = hn;
            __nv_bfloat16 hb = __float2bfloat16(hn);
            hhi[cta * HH + u] = hb;
            hlo[cta * HH + u] = __float2bfloat16(hn - __bfloat162float(hb));
        }
        __threadfence();
    }
}

// ---------------- launch ----------------
extern "C" void kernel_launch(void* const* d_in, const int* in_sizes, int n_in,
                              void* d_out, int out_size) {
    const float* x  = (const float*)d_in[0];  // [B,T,I]
    const float* h0 = (const float*)d_in[1];  // [B,H]
    const float* Wx = (const float*)d_in[2];  // [3H,I]
    const float* bx = (const float*)d_in[3];  // [3H]
    const float* Wh = (const float*)d_in[4];  // [3H,H]
    float* out = (float*)d_out;

    float *xlin, *part;
    __nv_bfloat16 *xhi, *xlo, *wxhi, *wxlo, *whhi, *whlo, *hhi, *hlo;
    cudaGetSymbolAddress((void**)&xlin, g_xlin);
    cudaGetSymbolAddress((void**)&part, g_part);
    cudaGetSymbolAddress((void**)&xhi, g_xhi);
    cudaGetSymbolAddress((void**)&xlo, g_xlo);
    cudaGetSymbolAddress((void**)&wxhi, g_wxhi);
    cudaGetSymbolAddress((void**)&wxlo, g_wxlo);
    cudaGetSymbolAddress((void**)&whhi, g_whhi);
    cudaGetSymbolAddress((void**)&whlo, g_whlo);
    cudaGetSymbolAddress((void**)&hhi, g_hhi);
    cudaGetSymbolAddress((void**)&hlo, g_hlo);

    cudaFuncSetAttribute(gemm_xlin_mma, cudaFuncAttributeMaxDynamicSharedMemorySize,
                         2 * BUF_B);
    cudaFuncSetAttribute(gru_persist_mma, cudaFuncAttributeMaxDynamicSharedMemorySize,
                         4 * T2 * 2);

    reset_bar<<<1, 1>>>();
    split_h0<<<(BB * HH + 255) / 256, 256>>>(h0, hhi, hlo, BB * HH);

    // bf16 hi/lo splits for x, Wx, Wh
    {
        int n2x = (BB * TT * II) / 2;
        split_bf16<<<(n2x + 255) / 256, 256>>>(x, xhi, xlo, n2x);
        int n2w = (H3 * II) / 2;
        split_bf16<<<(n2w + 255) / 256, 256>>>(Wx, wxhi, wxlo, n2w);
        int n2h = (H3 * HH) / 2;
        split_bf16<<<(n2h + 255) / 256, 256>>>(Wh, whhi, whlo, n2h);
    }

    // phase 1: tensor-core (HMMA) input projections
    gemm_xlin_mma<<<dim3(H3 / 128, (BB * TT) / 128), 256, 2 * BUF_B>>>(
        xhi, xlo, wxhi, wxlo, bx, xlin);

    // phase 2: persistent HMMA recurrence
    gru_persist_mma<<<NCTA, 256, 4 * T2 * 2>>>(xlin, whhi, whlo, h0, hhi, hlo,
                                               part, out);

    // h_final = y[:, T-1, :]
    if (out_size >= (int)((size_t)BB * TT * HH + BB * HH)) {
        copy_hfinal<<<(BB * HH + 255) / 256, 256>>>(out, out + (size_t)BB * TT * HH,
                                                    BB * HH);
    }
}

// round 8
// speedup vs baseline: 3.1462x; 1.0722x over previous
#include <cuda_runtime.h>
#include <cuda_bf16.h>
#include <math.h>
#include <cstdint>

#define BB 128
#define TT 512
#define II 512
#define HH 512
#define H3 1536
#define KK 512
#define NCTA 128

// ---------------- scratch (device globals: allocation-free) ----------------
__device__ float g_xlin[(size_t)BB * TT * H3];            // [B,T,3H]
__device__ __nv_bfloat16 g_hhi[BB * HH];                  // h hi
__device__ __nv_bfloat16 g_hlo[BB * HH];                  // h lo
__device__ __nv_bfloat16 g_xhi[(size_t)BB * TT * II];     // x hi
__device__ __nv_bfloat16 g_xlo[(size_t)BB * TT * II];     // x lo
__device__ __nv_bfloat16 g_wxhi[H3 * II];                 // Wx hi
__device__ __nv_bfloat16 g_wxlo[H3 * II];                 // Wx lo
__device__ __nv_bfloat16 g_whhi[H3 * HH];                 // Wh hi  [N=1536][K=512]
__device__ __nv_bfloat16 g_whlo[H3 * HH];                 // Wh lo
__device__ float g_part[(size_t)8 * BB * H3];             // K-split partials 6.3MB
__device__ int g_bar_count;

// ================= PTX helpers (baseline ISA only: sm_80+) =================
#define CP_ASYNC16(dst, src) \
    asm volatile("cp.async.cg.shared.global [%0], [%1], 16;" \
                 :: "r"(dst), "l"(src) : "memory")
#define CP_COMMIT() asm volatile("cp.async.commit_group;" ::: "memory")
template <int N>
__device__ __forceinline__ void cp_wait() {
    asm volatile("cp.async.wait_group %0;" :: "n"(N) : "memory");
}

__device__ __forceinline__ uint32_t smem_to_u32(const void* p) {
    uint32_t a;
    asm("{ .reg .u64 t; cvta.to.shared.u64 t, %1; cvt.u32.u64 %0, t; }"
        : "=r"(a) : "l"(p));
    return a;
}

__device__ __forceinline__ void ldmatrix_x4(uint32_t& r0, uint32_t& r1,
                                            uint32_t& r2, uint32_t& r3,
                                            uint32_t addr) {
    asm volatile("ldmatrix.sync.aligned.m8n8.x4.shared.b16 {%0,%1,%2,%3}, [%4];"
                 : "=r"(r0), "=r"(r1), "=r"(r2), "=r"(r3) : "r"(addr));
}

__device__ __forceinline__ void mma_bf16(float* c, const uint32_t* a,
                                         const uint32_t* b) {
    asm volatile(
        "mma.sync.aligned.m16n8k16.row.col.f32.bf16.bf16.f32 "
        "{%0,%1,%2,%3}, {%4,%5,%6,%7}, {%8,%9}, {%0,%1,%2,%3};"
        : "+f"(c[0]), "+f"(c[1]), "+f"(c[2]), "+f"(c[3])
        : "r"(a[0]), "r"(a[1]), "r"(a[2]), "r"(a[3]), "r"(b[0]), "r"(b[1]));
}

// ---------------- small helpers ----------------
__global__ void reset_bar() { g_bar_count = 0; }

// h_final gather: dst[b*H+u] = y[b, T-1, u]
__global__ void copy_hfinal(const float* __restrict__ y, float* __restrict__ dst,
                            int n) {
    int i = blockIdx.x * blockDim.x + threadIdx.x;
    if (i >= n) return;
    int b = i >> 9;
    int u = i & 511;
    dst[i] = y[((size_t)b * TT + (TT - 1)) * HH + u];
}

// h0 -> bf16 hi/lo split
__global__ void split_h0(const float* __restrict__ h0,
                         __nv_bfloat16* __restrict__ hhi,
                         __nv_bfloat16* __restrict__ hlo, int n) {
    int i = blockIdx.x * blockDim.x + threadIdx.x;
    if (i >= n) return;
    float v = h0[i];
    __nv_bfloat16 hb = __float2bfloat16(v);
    hhi[i] = hb;
    hlo[i] = __float2bfloat16(v - __bfloat162float(hb));
}

// combined fp32 -> bf16 hi/lo split for x, Wx, Wh (2 elems per thread)
#define NX2 ((size_t)BB * TT * II / 2)
#define NW2 ((size_t)H3 * II / 2)
#define NH2 ((size_t)H3 * HH / 2)
__global__ void split_all(const float* __restrict__ x,
                          const float* __restrict__ wx,
                          const float* __restrict__ wh,
                          __nv_bfloat16* __restrict__ xhi,
                          __nv_bfloat16* __restrict__ xlo,
                          __nv_bfloat16* __restrict__ wxhi,
                          __nv_bfloat16* __restrict__ wxlo,
                          __nv_bfloat16* __restrict__ whhi,
                          __nv_bfloat16* __restrict__ whlo) {
    size_t i = (size_t)blockIdx.x * blockDim.x + threadIdx.x;
    const float* src;
    __nv_bfloat16 *hi, *lo;
    size_t j;
    if (i < NX2) {
        src = x; hi = xhi; lo = xlo; j = i;
    } else if (i < NX2 + NW2) {
        src = wx; hi = wxhi; lo = wxlo; j = i - NX2;
    } else if (i < NX2 + NW2 + NH2) {
        src = wh; hi = whhi; lo = whlo; j = i - NX2 - NW2;
    } else {
        return;
    }
    float2 v = ((const float2*)src)[j];
    __nv_bfloat16 h0 = __float2bfloat16(v.x);
    __nv_bfloat16 h1 = __float2bfloat16(v.y);
    ((__nv_bfloat162*)hi)[j] = __nv_bfloat162(h0, h1);
    ((__nv_bfloat162*)lo)[j] =
        __nv_bfloat162(__float2bfloat16(v.x - __bfloat162float(h0)),
                       __float2bfloat16(v.y - __bfloat162float(h1)));
}

// ---------------- Phase 1: bf16-split GEMM via mma.sync (v3) ----------
// CTA tile 128m x 64n, 8 warps (2x4), warp tile 64x16 -> 32 acc regs.
// BK=32, 2-stage cp.async, one __syncthreads per chunk. occ 2.
#define SA 40                               // row stride in bf16 (80 B)
#define A_T (128 * SA * 2)                  // 10240 B per A component
#define B_T (64 * SA * 2)                   // 5120 B per B component
#define STG_B (2 * A_T + 2 * B_T)           // 30720 B per stage
#define O_AH 0
#define O_AL A_T
#define O_BH (2 * A_T)
#define O_BL (2 * A_T + B_T)

__global__ void __launch_bounds__(256, 2) gemm_xlin_mma(
    const __nv_bfloat16* __restrict__ Ahi, const __nv_bfloat16* __restrict__ Alo,
    const __nv_bfloat16* __restrict__ Bhi, const __nv_bfloat16* __restrict__ Blo,
    const float* __restrict__ bias, float* __restrict__ C) {
    extern __shared__ char smem[];
    const uint32_t sb = smem_to_u32(smem);

    const int tid = threadIdx.x;
    const int wid = tid >> 5;
    const int lane = tid & 31;
    const int wrow = wid >> 2;              // 0..1  (64 m each)
    const int wcol = wid & 3;               // 0..3  (16 n each)
    const int n0 = blockIdx.x * 64;
    const int m0 = blockIdx.y * 128;

    const __nv_bfloat16* ga_h = Ahi + (size_t)m0 * KK;
    const __nv_bfloat16* ga_l = Alo + (size_t)m0 * KK;
    const __nv_bfloat16* gb_h = Bhi + (size_t)n0 * KK;
    const __nv_bfloat16* gb_l = Blo + (size_t)n0 * KK;

    const int ra = tid >> 1;                // A row 0..127
    const int ga2 = (tid & 1) * 2;          // 2 x 16B groups
    const int rb = tid >> 2;                // B row 0..63
    const int gb1 = tid & 3;                // 1 x 16B group

    auto stage = [&](int kc, int buf) {
        const uint32_t d = sb + buf * STG_B;
        const __nv_bfloat16* sa_h = ga_h + (size_t)ra * KK + kc * 32;
        const __nv_bfloat16* sa_l = ga_l + (size_t)ra * KK + kc * 32;
        CP_ASYNC16(d + O_AH + ra * 80 + ga2 * 16, (const void*)(sa_h + ga2 * 8));
        CP_ASYNC16(d + O_AH + ra * 80 + (ga2 + 1) * 16, (const void*)(sa_h + (ga2 + 1) * 8));
        CP_ASYNC16(d + O_AL + ra * 80 + ga2 * 16, (const void*)(sa_l + ga2 * 8));
        CP_ASYNC16(d + O_AL + ra * 80 + (ga2 + 1) * 16, (const void*)(sa_l + (ga2 + 1) * 8));
        const __nv_bfloat16* sb_h = gb_h + (size_t)rb * KK + kc * 32;
        const __nv_bfloat16* sb_l = gb_l + (size_t)rb * KK + kc * 32;
        CP_ASYNC16(d + O_BH + rb * 80 + gb1 * 16, (const void*)(sb_h + gb1 * 8));
        CP_ASYNC16(d + O_BL + rb * 80 + gb1 * 16, (const void*)(sb_l + gb1 * 8));
        CP_COMMIT();
    };

    float acc[4][2][4];
#pragma unroll
    for (int i = 0; i < 4; i++)
#pragma unroll
        for (int j = 0; j < 2; j++)
#pragma unroll
            for (int q = 0; q < 4; q++) acc[i][j][q] = 0.f;

    const int lrow = lane & 15;
    const int lcol8 = (lane >> 4) * 8;

    stage(0, 0);

    const int NCHUNK = KK / 32;             // 16
    for (int kc = 0; kc < NCHUNK; kc++) {
        const int buf = kc & 1;
        __syncthreads();                    // prior compute done before restaging
        if (kc + 1 < NCHUNK) {
            stage(kc + 1, buf ^ 1);
            cp_wait<1>();
        } else {
            cp_wait<0>();
        }
        __syncthreads();                    // staged data visible

        const uint32_t bb = sb + buf * STG_B;
#pragma unroll
        for (int ks = 0; ks < 2; ks++) {
            const uint32_t coloff = (ks * 16 + lcol8) * 2;
            // B fragments: 2 n-tiles x {hi,lo}, one ldmatrix each comp
            uint32_t bh[2][2], bl[2][2];
            {
                const uint32_t brow = (wcol * 16 + lrow) * 80;
                uint32_t r0, r1, r2, r3;
                ldmatrix_x4(r0, r1, r2, r3, bb + O_BH + brow + coloff);
                bh[0][0] = r0; bh[1][0] = r1; bh[0][1] = r2; bh[1][1] = r3;
                ldmatrix_x4(r0, r1, r2, r3, bb + O_BL + brow + coloff);
                bl[0][0] = r0; bl[1][0] = r1; bl[0][1] = r2; bl[1][1] = r3;
            }
#pragma unroll
            for (int mt = 0; mt < 4; mt++) {
                const uint32_t arow = (wrow * 64 + mt * 16 + lrow) * 80;
                uint32_t ah[4], al[4];
                ldmatrix_x4(ah[0], ah[1], ah[2], ah[3], bb + O_AH + arow + coloff);
                ldmatrix_x4(al[0], al[1], al[2], al[3], bb + O_AL + arow + coloff);
#pragma unroll
                for (int nt = 0; nt < 2; nt++) {
                    mma_bf16(acc[mt][nt], ah, bh[nt]);
                    mma_bf16(acc[mt][nt], ah, bl[nt]);
                    mma_bf16(acc[mt][nt], al, bh[nt]);
                }
            }
        }
    }

    // epilogue
    const int erow = m0 + wrow * 64 + (lane >> 2);
    const int ecol0 = n0 + wcol * 16 + (lane & 3) * 2;
#pragma unroll
    for (int mt = 0; mt < 4; mt++) {
#pragma unroll
        for (int nt = 0; nt < 2; nt++) {
            const int col = ecol0 + nt * 8;
            const float b0 = bias[col], b1 = bias[col + 1];
            const int r0 = erow + mt * 16;
            *(float2*)(C + (size_t)r0 * H3 + col) =
                make_float2(acc[mt][nt][0] + b0, acc[mt][nt][1] + b1);
            *(float2*)(C + (size_t)(r0 + 8) * H3 + col) =
                make_float2(acc[mt][nt][2] + b0, acc[mt][nt][3] + b1);
        }
    }
}

// ---------------- grid-wide barrier: monotonic RED + poll ----------------
__device__ __forceinline__ void grid_barrier(int phase) {
    __syncthreads();
    if (threadIdx.x == 0) {
        __threadfence();                       // release (block's writes)
        atomicAdd(&g_bar_count, 1);            // return unused -> RED
        const int target = NCTA * phase;
        while (*((volatile int*)&g_bar_count) < target) { }
        __threadfence();                       // acquire
    }
    __syncthreads();
}

// ---------------- Phase 2: persistent HMMA recurrence ----------------
#define SA2 72
#define T2 (128 * SA2)

__global__ void __launch_bounds__(256, 1) gru_persist_mma(
    const float* __restrict__ xlin,
    const __nv_bfloat16* __restrict__ whhi,
    const __nv_bfloat16* __restrict__ whlo,
    const float* __restrict__ h0,
    __nv_bfloat16* __restrict__ hhi,
    __nv_bfloat16* __restrict__ hlo,
    float* __restrict__ part,
    float* __restrict__ y) {
    extern __shared__ __nv_bfloat16 sm2[];
    const uint32_t sb = smem_to_u32(sm2);

    const int tid = threadIdx.x;
    const int lane = tid & 31;
    const int wid = tid >> 5;
    const int wrow = wid >> 2;
    const int wcol = wid & 3;
    const int cta = blockIdx.x;
    const bool act = cta < 96;
    const int nt = cta >> 3;
    const int ks = cta & 7;
    const int lrow = lane & 15;
    const int lcol8 = (lane >> 4) * 8;

    // reg-carried h state for phase B
    float hold[2];
    hold[0] = h0[cta * HH + tid];
    hold[1] = h0[cta * HH + tid + 256];

    // ---- stage persistent Wh tiles (hi at 2*T2, lo at 3*T2) ----
    if (act) {
        const int row = tid >> 1;
        const int seg = tid & 1;
        const __nv_bfloat16* s0 = whhi + (size_t)(nt * 128 + row) * KK + ks * 64 + seg * 32;
        const __nv_bfloat16* s1 = whlo + (size_t)(nt * 128 + row) * KK + ks * 64 + seg * 32;
        uint32_t d0 = sb + (uint32_t)(2 * T2 + row * SA2 + seg * 32) * 2;
        uint32_t d1 = sb + (uint32_t)(3 * T2 + row * SA2 + seg * 32) * 2;
#pragma unroll
        for (int j = 0; j < 4; j++) {
            CP_ASYNC16(d0 + j * 16, (const void*)(s0 + j * 8));
            CP_ASYNC16(d1 + j * 16, (const void*)(s1 + j * 8));
        }
        CP_COMMIT();
        cp_wait<0>();
    }
    __syncthreads();

    for (int t = 0; t < TT; t++) {
        grid_barrier(2 * t + 1);        // h splits from prev step visible

        // ---- prefetch phase-B gate operands (hide under phase A) ----
        float pxz[2], pxr[2], pxn[2];
        {
            const float* xl = xlin + ((size_t)cta * TT + t) * H3;
#pragma unroll
            for (int uu = 0; uu < 2; uu++) {
                const int u = tid + uu * 256;
                pxz[uu] = xl[u];
                pxr[uu] = xl[u + 512];
                pxn[uu] = xl[u + 1024];
            }
        }

        if (act) {
            // ---- stage A = h splits [128 b x 64 k] (hi at 0, lo at T2) ----
            const int row = tid >> 1;
            const int seg = tid & 1;
            const __nv_bfloat16* s0 = hhi + row * HH + ks * 64 + seg * 32;
            const __nv_bfloat16* s1 = hlo + row * HH + ks * 64 + seg * 32;
            uint32_t d0 = sb + (uint32_t)(row * SA2 + seg * 32) * 2;
            uint32_t d1 = sb + (uint32_t)(T2 + row * SA2 + seg * 32) * 2;
#pragma unroll
            for (int j = 0; j < 4; j++) {
                CP_ASYNC16(d0 + j * 16, (const void*)(s0 + j * 8));
                CP_ASYNC16(d1 + j * 16, (const void*)(s1 + j * 8));
            }
            CP_COMMIT();
            cp_wait<0>();
            __syncthreads();

            float acc[4][4][4];
#pragma unroll
            for (int i = 0; i < 4; i++)
#pragma unroll
                for (int j = 0; j < 4; j++)
#pragma unroll
                    for (int q = 0; q < 4; q++) acc[i][j][q] = 0.f;

#pragma unroll
            for (int k16 = 0; k16 < 4; k16++) {
                const uint32_t coloff = (k16 * 16 + lcol8) * 2;
                uint32_t bh[4][2], bl[4][2];
#pragma unroll
                for (int half = 0; half < 2; half++) {
                    const uint32_t brow = (wcol * 32 + half * 16 + lrow) * (SA2 * 2);
                    uint32_t r0, r1, r2, r3;
                    ldmatrix_x4(r0, r1, r2, r3, sb + 2 * T2 * 2 + brow + coloff);
                    bh[half * 2 + 0][0] = r0; bh[half * 2 + 1][0] = r1;
                    bh[half * 2 + 0][1] = r2; bh[half * 2 + 1][1] = r3;
                    ldmatrix_x4(r0, r1, r2, r3, sb + 3 * T2 * 2 + brow + coloff);
                    bl[half * 2 + 0][0] = r0; bl[half * 2 + 1][0] = r1;
                    bl[half * 2 + 0][1] = r2; bl[half * 2 + 1][1] = r3;
                }
#pragma unroll
                for (int mt = 0; mt < 4; mt++) {
                    const uint32_t arow = (wrow * 64 + mt * 16 + lrow) * (SA2 * 2);
                    uint32_t ah[4], al[4];
                    ldmatrix_x4(ah[0], ah[1], ah[2], ah[3], sb + arow + coloff);
                    ldmatrix_x4(al[0], al[1], al[2], al[3], sb + T2 * 2 + arow + coloff);
#pragma unroll
                    for (int ntt = 0; ntt < 4; ntt++) {
                        mma_bf16(acc[mt][ntt], ah, bh[ntt]);
                        mma_bf16(acc[mt][ntt], ah, bl[ntt]);
                        mma_bf16(acc[mt][ntt], al, bh[ntt]);
                    }
                }
            }

            // ---- epilogue: partials to gmem [ks][128][1536] ----
            const int erow = wrow * 64 + (lane >> 2);
            const int ecol0 = nt * 128 + wcol * 32 + (lane & 3) * 2;
#pragma unroll
            for (int mt = 0; mt < 4; mt++) {
#pragma unroll
                for (int ntt = 0; ntt < 4; ntt++) {
                    const int col = ecol0 + ntt * 8;
                    const int r0 = erow + mt * 16;
                    *(float2*)(part + ((size_t)ks * BB + r0) * H3 + col) =
                        make_float2(acc[mt][ntt][0], acc[mt][ntt][1]);
                    *(float2*)(part + ((size_t)ks * BB + r0 + 8) * H3 + col) =
                        make_float2(acc[mt][ntt][2], acc[mt][ntt][3]);
                }
            }
            __syncthreads();   // smem A reuse safety for next step
        }

        grid_barrier(2 * t + 2);        // partials visible (release via barrier)

        // ---- phase B: CTA = batch, 2 units per thread ----
#pragma unroll
        for (int uu = 0; uu < 2; uu++) {
            const int u = tid + uu * 256;
            float az = 0.f, ar = 0.f, an = 0.f;
#pragma unroll
            for (int q = 0; q < 8; q++) {
                const float* pp = part + ((size_t)q * BB + cta) * H3 + u;
                az += __ldcg(pp);
                ar += __ldcg(pp + 512);
                an += __ldcg(pp + 1024);
            }
            float z = 1.f / (1.f + __expf(-(pxz[uu] + az)));
            float r = 1.f / (1.f + __expf(-(pxr[uu] + ar)));
            float n = tanhf(pxn[uu] + r * an);
            float hn = fmaf(z, hold[uu] - n, n);
            hold[uu] = hn;
            y[((size_t)cta * TT + t) * HH + u] = hn;
            __nv_bfloat16 hb = __float2bfloat16(hn);
            hhi[cta * HH + u] = hb;
            hlo[cta * HH + u] = __float2bfloat16(hn - __bfloat162float(hb));
        }
    }
}

// ---------------- launch ----------------
extern "C" void kernel_launch(void* const* d_in, const int* in_sizes, int n_in,
                              void* d_out, int out_size) {
    const float* x  = (const float*)d_in[0];  // [B,T,I]
    const float* h0 = (const float*)d_in[1];  // [B,H]
    const float* Wx = (const float*)d_in[2];  // [3H,I]
    const float* bx = (const float*)d_in[3];  // [3H]
    const float* Wh = (const float*)d_in[4];  // [3H,H]
    float* out = (float*)d_out;

    float *xlin, *part;
    __nv_bfloat16 *xhi, *xlo, *wxhi, *wxlo, *whhi, *whlo, *hhi, *hlo;
    cudaGetSymbolAddress((void**)&xlin, g_xlin);
    cudaGetSymbolAddress((void**)&part, g_part);
    cudaGetSymbolAddress((void**)&xhi, g_xhi);
    cudaGetSymbolAddress((void**)&xlo, g_xlo);
    cudaGetSymbolAddress((void**)&wxhi, g_wxhi);
    cudaGetSymbolAddress((void**)&wxlo, g_wxlo);
    cudaGetSymbolAddress((void**)&whhi, g_whhi);
    cudaGetSymbolAddress((void**)&whlo, g_whlo);
    cudaGetSymbolAddress((void**)&hhi, g_hhi);
    cudaGetSymbolAddress((void**)&hlo, g_hlo);

    cudaFuncSetAttribute(gemm_xlin_mma, cudaFuncAttributeMaxDynamicSharedMemorySize,
                         2 * STG_B);
    cudaFuncSetAttribute(gru_persist_mma, cudaFuncAttributeMaxDynamicSharedMemorySize,
                         4 * T2 * 2);

    // launch order chosen so the captured launch (index 3) is the GEMM
    reset_bar<<<1, 1>>>();                                              // 0
    split_h0<<<(BB * HH + 255) / 256, 256>>>(h0, hhi, hlo, BB * HH);    // 1
    {
        size_t tot = NX2 + NW2 + NH2;
        split_all<<<(unsigned)((tot + 255) / 256), 256>>>(              // 2
            x, Wx, Wh, xhi, xlo, wxhi, wxlo, whhi, whlo);
    }
    gemm_xlin_mma<<<dim3(H3 / 64, (BB * TT) / 128), 256, 2 * STG_B>>>(  // 3
        xhi, xlo, wxhi, wxlo, bx, xlin);
    gru_persist_mma<<<NCTA, 256, 4 * T2 * 2>>>(xlin, whhi, whlo, h0,    // 4
                                               hhi, hlo, part, out);
    if (out_size >= (int)((size_t)BB * TT * HH + BB * HH)) {
        copy_hfinal<<<(BB * HH + 255) / 256, 256>>>(out, out + (size_t)BB * TT * HH,
                                                    BB * HH);           // 5
    }
}

// round 9
// speedup vs baseline: 3.8088x; 1.2106x over previous
#include <cuda_runtime.h>
#include <cuda_bf16.h>
#include <cuda_fp16.h>
#include <math.h>
#include <cstdint>

#define BB 128
#define TT 512
#define II 512
#define HH 512
#define H3 1536
#define KK 512
#define NCTA 128

// ---------------- scratch (device globals: allocation-free) ----------------
__device__ float g_xlin[(size_t)BB * TT * H3];            // [B,T,3H]
__device__ __half g_hf16[BB * HH];                        // h fp16 (single)
__device__ __nv_bfloat16 g_xhi[(size_t)BB * TT * II];     // x hi (bf16)
__device__ __nv_bfloat16 g_xlo[(size_t)BB * TT * II];     // x lo
__device__ __nv_bfloat16 g_wxhi[H3 * II];                 // Wx hi
__device__ __nv_bfloat16 g_wxlo[H3 * II];                 // Wx lo
__device__ __half g_whh16[H3 * KK];                       // Wh hi (fp16)
__device__ __half g_whl16[H3 * KK];                       // Wh lo (fp16, x2^11)
__device__ float g_part[(size_t)8 * BB * H3];             // K-split partials
__device__ int g_bar_count;

// ================= PTX helpers (baseline ISA only: sm_80+) =================
#define CP_ASYNC16(dst, src) \
    asm volatile("cp.async.cg.shared.global [%0], [%1], 16;" \
                 :: "r"(dst), "l"(src) : "memory")
#define CP_COMMIT() asm volatile("cp.async.commit_group;" ::: "memory")
template <int N>
__device__ __forceinline__ void cp_wait() {
    asm volatile("cp.async.wait_group %0;" :: "n"(N) : "memory");
}

__device__ __forceinline__ uint32_t smem_to_u32(const void* p) {
    uint32_t a;
    asm("{ .reg .u64 t; cvta.to.shared.u64 t, %1; cvt.u32.u64 %0, t; }"
        : "=r"(a) : "l"(p));
    return a;
}

__device__ __forceinline__ void ldmatrix_x4(uint32_t& r0, uint32_t& r1,
                                            uint32_t& r2, uint32_t& r3,
                                            uint32_t addr) {
    asm volatile("ldmatrix.sync.aligned.m8n8.x4.shared.b16 {%0,%1,%2,%3}, [%4];"
                 : "=r"(r0), "=r"(r1), "=r"(r2), "=r"(r3) : "r"(addr));
}

__device__ __forceinline__ void mma_bf16(float* c, const uint32_t* a,
                                         const uint32_t* b) {
    asm volatile(
        "mma.sync.aligned.m16n8k16.row.col.f32.bf16.bf16.f32 "
        "{%0,%1,%2,%3}, {%4,%5,%6,%7}, {%8,%9}, {%0,%1,%2,%3};"
        : "+f"(c[0]), "+f"(c[1]), "+f"(c[2]), "+f"(c[3])
        : "r"(a[0]), "r"(a[1]), "r"(a[2]), "r"(a[3]), "r"(b[0]), "r"(b[1]));
}

__device__ __forceinline__ void mma_f16(float* c, const uint32_t* a,
                                        const uint32_t* b) {
    asm volatile(
        "mma.sync.aligned.m16n8k16.row.col.f32.f16.f16.f32 "
        "{%0,%1,%2,%3}, {%4,%5,%6,%7}, {%8,%9}, {%0,%1,%2,%3};"
        : "+f"(c[0]), "+f"(c[1]), "+f"(c[2]), "+f"(c[3])
        : "r"(a[0]), "r"(a[1]), "r"(a[2]), "r"(a[3]), "r"(b[0]), "r"(b[1]));
}

// ---------------- small helpers ----------------
__global__ void reset_bar() { g_bar_count = 0; }

// h_final gather: dst[b*H+u] = y[b, T-1, u]
__global__ void copy_hfinal(const float* __restrict__ y, float* __restrict__ dst,
                            int n) {
    int i = blockIdx.x * blockDim.x + threadIdx.x;
    if (i >= n) return;
    int b = i >> 9;
    int u = i & 511;
    dst[i] = y[((size_t)b * TT + (TT - 1)) * HH + u];
}

// one combined split kernel: x->bf16x2, Wx->bf16x2, Wh->fp16x2, h0->fp16
#define NX2 ((size_t)BB * TT * II / 2)
#define NW2 ((size_t)H3 * II / 2)
#define NH2 ((size_t)H3 * KK / 2)
#define NH0 ((size_t)BB * HH / 2)
__global__ void split_all(const float* __restrict__ x,
                          const float* __restrict__ wx,
                          const float* __restrict__ wh,
                          const float* __restrict__ h0,
                          __nv_bfloat16* __restrict__ xhi,
                          __nv_bfloat16* __restrict__ xlo,
                          __nv_bfloat16* __restrict__ wxhi,
                          __nv_bfloat16* __restrict__ wxlo,
                          __half* __restrict__ whh16,
                          __half* __restrict__ whl16,
                          __half* __restrict__ hf16) {
    size_t i = (size_t)blockIdx.x * blockDim.x + threadIdx.x;
    if (i < NX2 + NW2) {
        const float* src;
        __nv_bfloat16 *hi, *lo;
        size_t j;
        if (i < NX2) { src = x; hi = xhi; lo = xlo; j = i; }
        else { src = wx; hi = wxhi; lo = wxlo; j = i - NX2; }
        float2 v = ((const float2*)src)[j];
        __nv_bfloat16 h0b = __float2bfloat16(v.x);
        __nv_bfloat16 h1b = __float2bfloat16(v.y);
        ((__nv_bfloat162*)hi)[j] = __nv_bfloat162(h0b, h1b);
        ((__nv_bfloat162*)lo)[j] =
            __nv_bfloat162(__float2bfloat16(v.x - __bfloat162float(h0b)),
                           __float2bfloat16(v.y - __bfloat162float(h1b)));
    } else if (i < NX2 + NW2 + NH2) {
        size_t j = i - NX2 - NW2;
        float2 v = ((const float2*)wh)[j];
        __half a = __float2half_rn(v.x);
        __half b = __float2half_rn(v.y);
        // lo pre-scaled by 2^11 to stay in fp16 normal range
        __half al = __float2half_rn((v.x - __half2float(a)) * 2048.0f);
        __half bl = __float2half_rn((v.y - __half2float(b)) * 2048.0f);
        ((__half2*)whh16)[j] = __halves2half2(a, b);
        ((__half2*)whl16)[j] = __halves2half2(al, bl);
    } else if (i < NX2 + NW2 + NH2 + NH0) {
        size_t j = i - NX2 - NW2 - NH2;
        float2 v = ((const float2*)h0)[j];
        ((__half2*)hf16)[j] = __halves2half2(__float2half_rn(v.x),
                                             __float2half_rn(v.y));
    }
}

// ---------------- Phase 1: bf16-split GEMM via mma.sync (proven v3) -------
#define SA 40
#define A_T (128 * SA * 2)
#define B_T (64 * SA * 2)
#define STG_B (2 * A_T + 2 * B_T)
#define O_AH 0
#define O_AL A_T
#define O_BH (2 * A_T)
#define O_BL (2 * A_T + B_T)

__global__ void __launch_bounds__(256, 2) gemm_xlin_mma(
    const __nv_bfloat16* __restrict__ Ahi, const __nv_bfloat16* __restrict__ Alo,
    const __nv_bfloat16* __restrict__ Bhi, const __nv_bfloat16* __restrict__ Blo,
    const float* __restrict__ bias, float* __restrict__ C) {
    extern __shared__ char smem[];
    const uint32_t sb = smem_to_u32(smem);

    const int tid = threadIdx.x;
    const int wid = tid >> 5;
    const int lane = tid & 31;
    const int wrow = wid >> 2;
    const int wcol = wid & 3;
    const int n0 = blockIdx.x * 64;
    const int m0 = blockIdx.y * 128;

    const __nv_bfloat16* ga_h = Ahi + (size_t)m0 * KK;
    const __nv_bfloat16* ga_l = Alo + (size_t)m0 * KK;
    const __nv_bfloat16* gb_h = Bhi + (size_t)n0 * KK;
    const __nv_bfloat16* gb_l = Blo + (size_t)n0 * KK;

    const int ra = tid >> 1;
    const int ga2 = (tid & 1) * 2;
    const int rb = tid >> 2;
    const int gb1 = tid & 3;

    auto stage = [&](int kc, int buf) {
        const uint32_t d = sb + buf * STG_B;
        const __nv_bfloat16* sa_h = ga_h + (size_t)ra * KK + kc * 32;
        const __nv_bfloat16* sa_l = ga_l + (size_t)ra * KK + kc * 32;
        CP_ASYNC16(d + O_AH + ra * 80 + ga2 * 16, (const void*)(sa_h + ga2 * 8));
        CP_ASYNC16(d + O_AH + ra * 80 + (ga2 + 1) * 16, (const void*)(sa_h + (ga2 + 1) * 8));
        CP_ASYNC16(d + O_AL + ra * 80 + ga2 * 16, (const void*)(sa_l + ga2 * 8));
        CP_ASYNC16(d + O_AL + ra * 80 + (ga2 + 1) * 16, (const void*)(sa_l + (ga2 + 1) * 8));
        const __nv_bfloat16* sb_h = gb_h + (size_t)rb * KK + kc * 32;
        const __nv_bfloat16* sb_l = gb_l + (size_t)rb * KK + kc * 32;
        CP_ASYNC16(d + O_BH + rb * 80 + gb1 * 16, (const void*)(sb_h + gb1 * 8));
        CP_ASYNC16(d + O_BL + rb * 80 + gb1 * 16, (const void*)(sb_l + gb1 * 8));
        CP_COMMIT();
    };

    float acc[4][2][4];
#pragma unroll
    for (int i = 0; i < 4; i++)
#pragma unroll
        for (int j = 0; j < 2; j++)
#pragma unroll
            for (int q = 0; q < 4; q++) acc[i][j][q] = 0.f;

    const int lrow = lane & 15;
    const int lcol8 = (lane >> 4) * 8;

    stage(0, 0);

    const int NCHUNK = KK / 32;
    for (int kc = 0; kc < NCHUNK; kc++) {
        const int buf = kc & 1;
        __syncthreads();
        if (kc + 1 < NCHUNK) {
            stage(kc + 1, buf ^ 1);
            cp_wait<1>();
        } else {
            cp_wait<0>();
        }
        __syncthreads();

        const uint32_t bb = sb + buf * STG_B;
#pragma unroll
        for (int ks = 0; ks < 2; ks++) {
            const uint32_t coloff = (ks * 16 + lcol8) * 2;
            uint32_t bh[2][2], bl[2][2];
            {
                const uint32_t brow = (wcol * 16 + lrow) * 80;
                uint32_t r0, r1, r2, r3;
                ldmatrix_x4(r0, r1, r2, r3, bb + O_BH + brow + coloff);
                bh[0][0] = r0; bh[1][0] = r1; bh[0][1] = r2; bh[1][1] = r3;
                ldmatrix_x4(r0, r1, r2, r3, bb + O_BL + brow + coloff);
                bl[0][0] = r0; bl[1][0] = r1; bl[0][1] = r2; bl[1][1] = r3;
            }
#pragma unroll
            for (int mt = 0; mt < 4; mt++) {
                const uint32_t arow = (wrow * 64 + mt * 16 + lrow) * 80;
                uint32_t ah[4], al[4];
                ldmatrix_x4(ah[0], ah[1], ah[2], ah[3], bb + O_AH + arow + coloff);
                ldmatrix_x4(al[0], al[1], al[2], al[3], bb + O_AL + arow + coloff);
#pragma unroll
                for (int nt = 0; nt < 2; nt++) {
                    mma_bf16(acc[mt][nt], ah, bh[nt]);
                    mma_bf16(acc[mt][nt], ah, bl[nt]);
                    mma_bf16(acc[mt][nt], al, bh[nt]);
                }
            }
        }
    }

    const int erow = m0 + wrow * 64 + (lane >> 2);
    const int ecol0 = n0 + wcol * 16 + (lane & 3) * 2;
#pragma unroll
    for (int mt = 0; mt < 4; mt++) {
#pragma unroll
        for (int nt = 0; nt < 2; nt++) {
            const int col = ecol0 + nt * 8;
            const float b0 = bias[col], b1 = bias[col + 1];
            const int r0 = erow + mt * 16;
            *(float2*)(C + (size_t)r0 * H3 + col) =
                make_float2(acc[mt][nt][0] + b0, acc[mt][nt][1] + b1);
            *(float2*)(C + (size_t)(r0 + 8) * H3 + col) =
                make_float2(acc[mt][nt][2] + b0, acc[mt][nt][3] + b1);
        }
    }
}

// ---------------- grid-wide barrier: monotonic RED + poll ----------------
__device__ __forceinline__ void grid_barrier(int phase) {
    __syncthreads();
    if (threadIdx.x == 0) {
        __threadfence();                       // release
        atomicAdd(&g_bar_count, 1);
        const int target = NCTA * phase;
        while (*((volatile int*)&g_bar_count) < target) { }
        __threadfence();                       // acquire
    }
    __syncthreads();
}

// ---------------- Phase 2: persistent fp16 2-pass HMMA recurrence ---------
// 128 CTAs x 256 threads. CTA = nt(0..15: 96 n-rows) x ks(0..7: 64 k).
// Wh fp16 hi/lo resident in smem; h staged per step as single fp16.
// Warp tile 32m x 48n (warps 4x2). acc_lo scaled by 2^-11 in epilogue.
// Phase B (CTA = batch): reduce 8 partials, gate, write y + h fp16.
#define RS 72                       // smem row stride in fp16 (144 B)
#define SM_A 0                      // A: 128 x RS fp16 = 18432 B
#define SM_BH (128 * RS * 2)        // Bhi: 96 x RS fp16 = 13824 B
#define SM_BL (SM_BH + 96 * RS * 2)
#define SM_TOT (SM_BL + 96 * RS * 2)   // 46080 B

__global__ void __launch_bounds__(256, 1) gru_persist_mma(
    const float* __restrict__ xlin,
    const __half* __restrict__ whh16,
    const __half* __restrict__ whl16,
    const float* __restrict__ h0,
    __half* __restrict__ hf16,
    float* __restrict__ part,
    float* __restrict__ y) {
    extern __shared__ __half smh[];
    const uint32_t sb = smem_to_u32(smh);

    const int tid = threadIdx.x;
    const int lane = tid & 31;
    const int wid = tid >> 5;
    const int wrow = wid >> 1;          // 0..3 (32 m each)
    const int wcol = wid & 1;           // 0..1 (48 n each)
    const int cta = blockIdx.x;
    const int nt = cta >> 3;            // 0..15
    const int ks = cta & 7;             // 0..7
    const int lrow = lane & 15;
    const int lcol8 = (lane >> 4) * 8;

    // reg-carried h state for phase B (batch = cta)
    float hold[2];
    hold[0] = h0[cta * HH + tid];
    hold[1] = h0[cta * HH + tid + 256];

    // ---- stage resident Wh tiles: rows [nt*96, +96), k cols [ks*64, +64) --
    {
#pragma unroll
        for (int i = 0; i < 3; i++) {
            int c = tid + i * 256;          // 0..767
            int row = c >> 3;               // 0..95
            int seg = c & 7;
            const __half* s0 = whh16 + (size_t)(nt * 96 + row) * KK + ks * 64 + seg * 8;
            const __half* s1 = whl16 + (size_t)(nt * 96 + row) * KK + ks * 64 + seg * 8;
            CP_ASYNC16(sb + SM_BH + (row * RS + seg * 8) * 2, (const void*)s0);
            CP_ASYNC16(sb + SM_BL + (row * RS + seg * 8) * 2, (const void*)s1);
        }
        CP_COMMIT();
        cp_wait<0>();
    }
    __syncthreads();

    for (int t = 0; t < TT; t++) {
        grid_barrier(2 * t + 1);        // prev step's h fp16 visible

        // ---- prefetch phase-B gate operands (hide under phase A) ----
        float pxz[2], pxr[2], pxn[2];
        {
            const float* xl = xlin + ((size_t)cta * TT + t) * H3;
#pragma unroll
            for (int uu = 0; uu < 2; uu++) {
                const int u = tid + uu * 256;
                pxz[uu] = xl[u];
                pxr[uu] = xl[u + 512];
                pxn[uu] = xl[u + 1024];
            }
        }

        // ---- stage A = h fp16 [128 b][64 k] ----
        {
#pragma unroll
            for (int i = 0; i < 4; i++) {
                int c = tid + i * 256;      // 0..1023
                int row = c >> 3;           // 0..127
                int seg = c & 7;
                const __half* s = hf16 + (size_t)row * HH + ks * 64 + seg * 8;
                CP_ASYNC16(sb + SM_A + (row * RS + seg * 8) * 2, (const void*)s);
            }
            CP_COMMIT();
            cp_wait<0>();
        }
        __syncthreads();

        // ---- 2-pass fp16 mma: hi (acc) and lo (accl, scaled 2^11) ----
        float acc[2][6][4], accl[2][6][4];
#pragma unroll
        for (int i = 0; i < 2; i++)
#pragma unroll
            for (int j = 0; j < 6; j++)
#pragma unroll
                for (int q = 0; q < 4; q++) { acc[i][j][q] = 0.f; accl[i][j][q] = 0.f; }

#pragma unroll
        for (int k16 = 0; k16 < 4; k16++) {
            const uint32_t coloff = (k16 * 16 + lcol8) * 2;
            uint32_t bh[6][2], bl[6][2];
#pragma unroll
            for (int pr = 0; pr < 3; pr++) {
                const uint32_t brow = (wcol * 48 + pr * 16 + lrow) * (RS * 2);
                uint32_t r0, r1, r2, r3;
                ldmatrix_x4(r0, r1, r2, r3, sb + SM_BH + brow + coloff);
                bh[pr * 2 + 0][0] = r0; bh[pr * 2 + 1][0] = r1;
                bh[pr * 2 + 0][1] = r2; bh[pr * 2 + 1][1] = r3;
                ldmatrix_x4(r0, r1, r2, r3, sb + SM_BL + brow + coloff);
                bl[pr * 2 + 0][0] = r0; bl[pr * 2 + 1][0] = r1;
                bl[pr * 2 + 0][1] = r2; bl[pr * 2 + 1][1] = r3;
            }
#pragma unroll
            for (int mt = 0; mt < 2; mt++) {
                const uint32_t arow = (wrow * 32 + mt * 16 + lrow) * (RS * 2);
                uint32_t a[4];
                ldmatrix_x4(a[0], a[1], a[2], a[3], sb + SM_A + arow + coloff);
#pragma unroll
                for (int ntt = 0; ntt < 6; ntt++) {
                    mma_f16(acc[mt][ntt], a, bh[ntt]);
                    mma_f16(accl[mt][ntt], a, bl[ntt]);
                }
            }
        }

        // ---- epilogue: partials (hi + lo*2^-11) to part[ks][128][1536] ----
        {
            const int erow = wrow * 32 + (lane >> 2);
            const int ecol0 = nt * 96 + wcol * 48 + (lane & 3) * 2;
            const float sc = 1.0f / 2048.0f;
#pragma unroll
            for (int mt = 0; mt < 2; mt++) {
#pragma unroll
                for (int ntt = 0; ntt < 6; ntt++) {
                    const int col = ecol0 + ntt * 8;
                    const int r0 = erow + mt * 16;
                    float v0 = fmaf(accl[mt][ntt][0], sc, acc[mt][ntt][0]);
                    float v1 = fmaf(accl[mt][ntt][1], sc, acc[mt][ntt][1]);
                    float v2 = fmaf(accl[mt][ntt][2], sc, acc[mt][ntt][2]);
                    float v3 = fmaf(accl[mt][ntt][3], sc, acc[mt][ntt][3]);
                    *(float2*)(part + ((size_t)ks * BB + r0) * H3 + col) =
                        make_float2(v0, v1);
                    *(float2*)(part + ((size_t)ks * BB + r0 + 8) * H3 + col) =
                        make_float2(v2, v3);
                }
            }
        }

        grid_barrier(2 * t + 2);        // partials visible

        // ---- phase B: CTA = batch, 2 units per thread ----
#pragma unroll
        for (int uu = 0; uu < 2; uu++) {
            const int u = tid + uu * 256;
            float az = 0.f, ar = 0.f, an = 0.f;
#pragma unroll
            for (int q = 0; q < 8; q++) {
                const float* pp = part + ((size_t)q * BB + cta) * H3 + u;
                az += __ldcg(pp);
                ar += __ldcg(pp + 512);
                an += __ldcg(pp + 1024);
            }
            float z = 1.f / (1.f + __expf(-(pxz[uu] + az)));
            float r = 1.f / (1.f + __expf(-(pxr[uu] + ar)));
            float n = tanhf(pxn[uu] + r * an);
            float hn = fmaf(z, hold[uu] - n, n);
            hold[uu] = hn;
            y[((size_t)cta * TT + t) * HH + u] = hn;
            hf16[cta * HH + u] = __float2half_rn(hn);
        }
    }
}

// ---------------- launch ----------------
extern "C" void kernel_launch(void* const* d_in, const int* in_sizes, int n_in,
                              void* d_out, int out_size) {
    const float* x  = (const float*)d_in[0];  // [B,T,I]
    const float* h0 = (const float*)d_in[1];  // [B,H]
    const float* Wx = (const float*)d_in[2];  // [3H,I]
    const float* bx = (const float*)d_in[3];  // [3H]
    const float* Wh = (const float*)d_in[4];  // [3H,H]
    float* out = (float*)d_out;

    float *xlin, *part;
    __nv_bfloat16 *xhi, *xlo, *wxhi, *wxlo;
    __half *whh16, *whl16, *hf16;
    cudaGetSymbolAddress((void**)&xlin, g_xlin);
    cudaGetSymbolAddress((void**)&part, g_part);
    cudaGetSymbolAddress((void**)&xhi, g_xhi);
    cudaGetSymbolAddress((void**)&xlo, g_xlo);
    cudaGetSymbolAddress((void**)&wxhi, g_wxhi);
    cudaGetSymbolAddress((void**)&wxlo, g_wxlo);
    cudaGetSymbolAddress((void**)&whh16, g_whh16);
    cudaGetSymbolAddress((void**)&whl16, g_whl16);
    cudaGetSymbolAddress((void**)&hf16, g_hf16);

    cudaFuncSetAttribute(gemm_xlin_mma, cudaFuncAttributeMaxDynamicSharedMemorySize,
                         2 * STG_B);
    cudaFuncSetAttribute(gru_persist_mma, cudaFuncAttributeMaxDynamicSharedMemorySize,
                         SM_TOT);

    // launch order: ncu captures index 3 -> that's the recurrence this round
    reset_bar<<<1, 1>>>();                                              // 0
    {
        size_t tot = NX2 + NW2 + NH2 + NH0;
        split_all<<<(unsigned)((tot + 255) / 256), 256>>>(              // 1
            x, Wx, Wh, h0, xhi, xlo, wxhi, wxlo, whh16, whl16, hf16);
    }
    gemm_xlin_mma<<<dim3(H3 / 64, (BB * TT) / 128), 256, 2 * STG_B>>>(  // 2
        xhi, xlo, wxhi, wxlo, bx, xlin);
    gru_persist_mma<<<NCTA, 256, SM_TOT>>>(xlin, whh16, whl16, h0,      // 3
                                           hf16, part, out);
    if (out_size >= (int)((size_t)BB * TT * HH + BB * HH)) {
        copy_hfinal<<<(BB * HH + 255) / 256, 256>>>(out, out + (size_t)BB * TT * HH,
                                                    BB * HH);           // 4
    }
}

// round 10
// speedup vs baseline: 4.6397x; 1.2181x over previous
#include <cuda_runtime.h>
#include <cuda_bf16.h>
#include <cuda_fp16.h>
#include <math.h>
#include <cstdint>

#define BB 128
#define TT 512
#define II 512
#define HH 512
#define H3 1536
#define KK 512
#define NCTA 128

// ---------------- scratch (device globals: allocation-free) ----------------
__device__ float g_xlin[(size_t)BB * TT * H3];            // [B,T,3H]
__device__ __half g_hb16[2][BB * HH];                     // h fp16 ping-pong
__device__ __nv_bfloat16 g_xhi[(size_t)BB * TT * II];     // x hi (bf16)
__device__ __nv_bfloat16 g_xlo[(size_t)BB * TT * II];     // x lo
__device__ __nv_bfloat16 g_wxhi[H3 * II];                 // Wx hi
__device__ __nv_bfloat16 g_wxlo[H3 * II];                 // Wx lo
__device__ __half g_whh16[H3 * KK];                       // Wh hi, gate-permuted rows
__device__ __half g_whl16[H3 * KK];                       // Wh lo (x2^11), permuted
__device__ int g_bar_count;

// ================= PTX helpers (baseline ISA only: sm_80+) =================
#define CP_ASYNC16(dst, src) \
    asm volatile("cp.async.cg.shared.global [%0], [%1], 16;" \
                 :: "r"(dst), "l"(src) : "memory")
#define CP_COMMIT() asm volatile("cp.async.commit_group;" ::: "memory")
template <int N>
__device__ __forceinline__ void cp_wait() {
    asm volatile("cp.async.wait_group %0;" :: "n"(N) : "memory");
}

__device__ __forceinline__ uint32_t smem_to_u32(const void* p) {
    uint32_t a;
    asm("{ .reg .u64 t; cvta.to.shared.u64 t, %1; cvt.u32.u64 %0, t; }"
        : "=r"(a) : "l"(p));
    return a;
}

__device__ __forceinline__ void ldmatrix_x4(uint32_t& r0, uint32_t& r1,
                                            uint32_t& r2, uint32_t& r3,
                                            uint32_t addr) {
    asm volatile("ldmatrix.sync.aligned.m8n8.x4.shared.b16 {%0,%1,%2,%3}, [%4];"
                 : "=r"(r0), "=r"(r1), "=r"(r2), "=r"(r3) : "r"(addr));
}

__device__ __forceinline__ void ldmatrix_x2(uint32_t& r0, uint32_t& r1,
                                            uint32_t addr) {
    asm volatile("ldmatrix.sync.aligned.m8n8.x2.shared.b16 {%0,%1}, [%2];"
                 : "=r"(r0), "=r"(r1) : "r"(addr));
}

__device__ __forceinline__ void mma_bf16(float* c, const uint32_t* a,
                                         const uint32_t* b) {
    asm volatile(
        "mma.sync.aligned.m16n8k16.row.col.f32.bf16.bf16.f32 "
        "{%0,%1,%2,%3}, {%4,%5,%6,%7}, {%8,%9}, {%0,%1,%2,%3};"
        : "+f"(c[0]), "+f"(c[1]), "+f"(c[2]), "+f"(c[3])
        : "r"(a[0]), "r"(a[1]), "r"(a[2]), "r"(a[3]), "r"(b[0]), "r"(b[1]));
}

__device__ __forceinline__ void mma_f16(float* c, const uint32_t* a,
                                        const uint32_t* b) {
    asm volatile(
        "mma.sync.aligned.m16n8k16.row.col.f32.f16.f16.f32 "
        "{%0,%1,%2,%3}, {%4,%5,%6,%7}, {%8,%9}, {%0,%1,%2,%3};"
        : "+f"(c[0]), "+f"(c[1]), "+f"(c[2]), "+f"(c[3])
        : "r"(a[0]), "r"(a[1]), "r"(a[2]), "r"(a[3]), "r"(b[0]), "r"(b[1]));
}

// ---------------- small helpers ----------------
__global__ void reset_bar() { g_bar_count = 0; }

__global__ void copy_hfinal(const float* __restrict__ y, float* __restrict__ dst,
                            int n) {
    int i = blockIdx.x * blockDim.x + threadIdx.x;
    if (i >= n) return;
    int b = i >> 9;
    int u = i & 511;
    dst[i] = y[((size_t)b * TT + (TT - 1)) * HH + u];
}

// combined split: x->bf16x2, Wx->bf16x2, Wh->fp16x2 gate-permuted, h0->fp16
#define NX2 ((size_t)BB * TT * II / 2)
#define NW2 ((size_t)H3 * II / 2)
#define NH2 ((size_t)H3 * KK / 2)
#define NH0 ((size_t)BB * HH / 2)
__global__ void split_all(const float* __restrict__ x,
                          const float* __restrict__ wx,
                          const float* __restrict__ wh,
                          const float* __restrict__ h0,
                          __nv_bfloat16* __restrict__ xhi,
                          __nv_bfloat16* __restrict__ xlo,
                          __nv_bfloat16* __restrict__ wxhi,
                          __nv_bfloat16* __restrict__ wxlo,
                          __half* __restrict__ whh16,
                          __half* __restrict__ whl16,
                          __half* __restrict__ hb0) {
    size_t i = (size_t)blockIdx.x * blockDim.x + threadIdx.x;
    if (i < NX2 + NW2) {
        const float* src;
        __nv_bfloat16 *hi, *lo;
        size_t j;
        if (i < NX2) { src = x; hi = xhi; lo = xlo; j = i; }
        else { src = wx; hi = wxhi; lo = wxlo; j = i - NX2; }
        float2 v = ((const float2*)src)[j];
        __nv_bfloat16 h0b = __float2bfloat16(v.x);
        __nv_bfloat16 h1b = __float2bfloat16(v.y);
        ((__nv_bfloat162*)hi)[j] = __nv_bfloat162(h0b, h1b);
        ((__nv_bfloat162*)lo)[j] =
            __nv_bfloat162(__float2bfloat16(v.x - __bfloat162float(h0b)),
                           __float2bfloat16(v.y - __bfloat162float(h1b)));
    } else if (i < NX2 + NW2 + NH2) {
        size_t j = i - NX2 - NW2;
        int g = (int)(j >> 8);            // Wh row 0..1535
        int k2 = (int)(j & 255);          // half2 col index
        int gate = g >> 9;
        int u = g & 511;
        int prow = (u >> 3) * 24 + gate * 8 + (u & 7);   // gate-permuted row
        float2 v = ((const float2*)wh)[j];
        __half a = __float2half_rn(v.x);
        __half b = __float2half_rn(v.y);
        __half al = __float2half_rn((v.x - __half2float(a)) * 2048.0f);
        __half bl = __float2half_rn((v.y - __half2float(b)) * 2048.0f);
        ((__half2*)whh16)[(size_t)prow * 256 + k2] = __halves2half2(a, b);
        ((__half2*)whl16)[(size_t)prow * 256 + k2] = __halves2half2(al, bl);
    } else if (i < NX2 + NW2 + NH2 + NH0) {
        size_t j = i - NX2 - NW2 - NH2;
        float2 v = ((const float2*)h0)[j];
        ((__half2*)hb0)[j] = __halves2half2(__float2half_rn(v.x),
                                            __float2half_rn(v.y));
    }
}

// ---------------- Phase 1: bf16-split GEMM via mma.sync (proven v3) -------
#define SA 40
#define A_T (128 * SA * 2)
#define B_T (64 * SA * 2)
#define STG_B (2 * A_T + 2 * B_T)
#define O_AH 0
#define O_AL A_T
#define O_BH (2 * A_T)
#define O_BL (2 * A_T + B_T)

__global__ void __launch_bounds__(256, 2) gemm_xlin_mma(
    const __nv_bfloat16* __restrict__ Ahi, const __nv_bfloat16* __restrict__ Alo,
    const __nv_bfloat16* __restrict__ Bhi, const __nv_bfloat16* __restrict__ Blo,
    const float* __restrict__ bias, float* __restrict__ C) {
    extern __shared__ char smem[];
    const uint32_t sb = smem_to_u32(smem);

    const int tid = threadIdx.x;
    const int wid = tid >> 5;
    const int lane = tid & 31;
    const int wrow = wid >> 2;
    const int wcol = wid & 3;
    const int n0 = blockIdx.x * 64;
    const int m0 = blockIdx.y * 128;

    const __nv_bfloat16* ga_h = Ahi + (size_t)m0 * KK;
    const __nv_bfloat16* ga_l = Alo + (size_t)m0 * KK;
    const __nv_bfloat16* gb_h = Bhi + (size_t)n0 * KK;
    const __nv_bfloat16* gb_l = Blo + (size_t)n0 * KK;

    const int ra = tid >> 1;
    const int ga2 = (tid & 1) * 2;
    const int rb = tid >> 2;
    const int gb1 = tid & 3;

    auto stage = [&](int kc, int buf) {
        const uint32_t d = sb + buf * STG_B;
        const __nv_bfloat16* sa_h = ga_h + (size_t)ra * KK + kc * 32;
        const __nv_bfloat16* sa_l = ga_l + (size_t)ra * KK + kc * 32;
        CP_ASYNC16(d + O_AH + ra * 80 + ga2 * 16, (const void*)(sa_h + ga2 * 8));
        CP_ASYNC16(d + O_AH + ra * 80 + (ga2 + 1) * 16, (const void*)(sa_h + (ga2 + 1) * 8));
        CP_ASYNC16(d + O_AL + ra * 80 + ga2 * 16, (const void*)(sa_l + ga2 * 8));
        CP_ASYNC16(d + O_AL + ra * 80 + (ga2 + 1) * 16, (const void*)(sa_l + (ga2 + 1) * 8));
        const __nv_bfloat16* sb_h = gb_h + (size_t)rb * KK + kc * 32;
        const __nv_bfloat16* sb_l = gb_l + (size_t)rb * KK + kc * 32;
        CP_ASYNC16(d + O_BH + rb * 80 + gb1 * 16, (const void*)(sb_h + gb1 * 8));
        CP_ASYNC16(d + O_BL + rb * 80 + gb1 * 16, (const void*)(sb_l + gb1 * 8));
        CP_COMMIT();
    };

    float acc[4][2][4];
#pragma unroll
    for (int i = 0; i < 4; i++)
#pragma unroll
        for (int j = 0; j < 2; j++)
#pragma unroll
            for (int q = 0; q < 4; q++) acc[i][j][q] = 0.f;

    const int lrow = lane & 15;
    const int lcol8 = (lane >> 4) * 8;

    stage(0, 0);

    const int NCHUNK = KK / 32;
    for (int kc = 0; kc < NCHUNK; kc++) {
        const int buf = kc & 1;
        __syncthreads();
        if (kc + 1 < NCHUNK) {
            stage(kc + 1, buf ^ 1);
            cp_wait<1>();
        } else {
            cp_wait<0>();
        }
        __syncthreads();

        const uint32_t bb = sb + buf * STG_B;
#pragma unroll
        for (int ks = 0; ks < 2; ks++) {
            const uint32_t coloff = (ks * 16 + lcol8) * 2;
            uint32_t bh[2][2], bl[2][2];
            {
                const uint32_t brow = (wcol * 16 + lrow) * 80;
                uint32_t r0, r1, r2, r3;
                ldmatrix_x4(r0, r1, r2, r3, bb + O_BH + brow + coloff);
                bh[0][0] = r0; bh[1][0] = r1; bh[0][1] = r2; bh[1][1] = r3;
                ldmatrix_x4(r0, r1, r2, r3, bb + O_BL + brow + coloff);
                bl[0][0] = r0; bl[1][0] = r1; bl[0][1] = r2; bl[1][1] = r3;
            }
#pragma unroll
            for (int mt = 0; mt < 4; mt++) {
                const uint32_t arow = (wrow * 64 + mt * 16 + lrow) * 80;
                uint32_t ah[4], al[4];
                ldmatrix_x4(ah[0], ah[1], ah[2], ah[3], bb + O_AH + arow + coloff);
                ldmatrix_x4(al[0], al[1], al[2], al[3], bb + O_AL + arow + coloff);
#pragma unroll
                for (int nt = 0; nt < 2; nt++) {
                    mma_bf16(acc[mt][nt], ah, bh[nt]);
                    mma_bf16(acc[mt][nt], ah, bl[nt]);
                    mma_bf16(acc[mt][nt], al, bh[nt]);
                }
            }
        }
    }

    const int erow = m0 + wrow * 64 + (lane >> 2);
    const int ecol0 = n0 + wcol * 16 + (lane & 3) * 2;
#pragma unroll
    for (int mt = 0; mt < 4; mt++) {
#pragma unroll
        for (int nt = 0; nt < 2; nt++) {
            const int col = ecol0 + nt * 8;
            const float b0 = bias[col], b1 = bias[col + 1];
            const int r0 = erow + mt * 16;
            *(float2*)(C + (size_t)r0 * H3 + col) =
                make_float2(acc[mt][nt][0] + b0, acc[mt][nt][1] + b1);
            *(float2*)(C + (size_t)(r0 + 8) * H3 + col) =
                make_float2(acc[mt][nt][2] + b0, acc[mt][nt][3] + b1);
        }
    }
}

// ---------------- grid-wide barrier: monotonic RED + poll ----------------
__device__ __forceinline__ void grid_barrier(int phase) {
    __syncthreads();
    if (threadIdx.x == 0) {
        __threadfence();                       // release
        atomicAdd(&g_bar_count, 1);
        const int target = NCTA * phase;
        while (*((volatile int*)&g_bar_count) < target) { }
        __threadfence();                       // acquire
    }
    __syncthreads();
}

// ---------------- Phase 2: fused full-K recurrence, ONE barrier/step ------
// 128 CTAs = 64 unit-groups x 2 batch-halves. CTA tile: 64b x 24n x 512k
// (24 permuted rows = 8 units x {z,r,n}). Warp (w): wm=w&3 m16-tile,
// wk=w>>2 K-half; intra-CTA k-reduce via smem. Gating fully register-local
// (c-fragment cols of the 3 n8-tiles are the SAME units). h ping-pong fp16.
#define RSA 520
#define RSB 520
#define SM_A 0
#define A_SZ (64 * RSA * 2)             // 66560
#define SM_BHI A_SZ
#define B_SZ (24 * RSB * 2)             // 24960
#define SM_BLO (SM_BHI + B_SZ)
#define SM_RED (SM_BLO + B_SZ)          // 116480
#define SMT (SM_RED + 4 * 32 * 13 * 4)  // 123136

__global__ void __launch_bounds__(256, 1) gru_persist_mma(
    const float* __restrict__ xlin,
    const __half* __restrict__ whh16,
    const __half* __restrict__ whl16,
    const float* __restrict__ h0,
    __half* __restrict__ hbuf,          // 2 x BB*HH fp16 ping-pong
    float* __restrict__ y) {
    extern __shared__ char smh[];
    const uint32_t sb = smem_to_u32(smh);
    float* red = (float*)(smh + SM_RED);

    const int tid = threadIdx.x;
    const int lane = tid & 31;
    const int wid = tid >> 5;
    const int wm = wid & 3;             // m16-tile 0..3
    const int wk = wid >> 2;            // K-half 0..1
    const int cta = blockIdx.x;
    const int ug = cta >> 1;            // unit group 0..63
    const int mh = cta & 1;             // batch half
    const int b0 = mh * 64;
    const int lrow = lane & 15;
    const int lcol8 = (lane >> 4) * 8;

    // gating ownership (wk==0 warps): 2 rows x 2 units
    const int gr0 = b0 + wm * 16 + (lane >> 2);      // +0, +8
    const int gu0 = ug * 8 + (lane & 3) * 2;         // +0, +1

    // reg-carried h_old [rh][ui]
    float hold[2][2];
    if (wk == 0) {
#pragma unroll
        for (int rh = 0; rh < 2; rh++)
#pragma unroll
            for (int ui = 0; ui < 2; ui++)
                hold[rh][ui] = h0[(gr0 + rh * 8) * HH + gu0 + ui];
    }

    // ---- stage resident permuted Wh tiles: rows [ug*24, +24) ----
    {
#pragma unroll
        for (int i = 0; i < 12; i++) {
            int c = tid + i * 256;            // 0..3071
            int comp = c >= 1536;
            int cc = comp ? c - 1536 : c;
            int row = cc >> 6;                // 0..23
            int seg = cc & 63;
            const __half* s = (comp ? whl16 : whh16) +
                              (size_t)(ug * 24 + row) * KK + seg * 8;
            uint32_t d = sb + (comp ? SM_BLO : SM_BHI) + (row * RSB + seg * 8) * 2;
            CP_ASYNC16(d, (const void*)s);
        }
        CP_COMMIT();
        cp_wait<0>();
    }
    __syncthreads();

    const float sc = 1.0f / 2048.0f;

    for (int t = 0; t < TT; t++) {
        // ---- prefetch xlin gate operands BEFORE barrier (constant data) ----
        float px[3][2][2];
        if (wk == 0) {
            const float* xlb0 = xlin + (size_t)t * H3;
#pragma unroll
            for (int rh = 0; rh < 2; rh++) {
                const float* xl = xlb0 + (size_t)(gr0 + rh * 8) * (TT * H3);
#pragma unroll
                for (int ui = 0; ui < 2; ui++) {
                    px[0][rh][ui] = xl[gu0 + ui];
                    px[1][rh][ui] = xl[gu0 + ui + 512];
                    px[2][rh][ui] = xl[gu0 + ui + 1024];
                }
            }
        }

        grid_barrier(t + 1);            // h(t-1) fp16 visible everywhere

        // ---- stage A = h fp16 [64b x 512k] from ping buffer ----
        {
            const __half* hsrc = hbuf + (size_t)(t & 1) * (BB * HH);
#pragma unroll
            for (int i = 0; i < 16; i++) {
                int c = tid + i * 256;        // 0..4095
                int row = c >> 6;             // 0..63
                int seg = c & 63;
                CP_ASYNC16(sb + SM_A + (row * RSA + seg * 8) * 2,
                           (const void*)(hsrc + (size_t)(b0 + row) * HH + seg * 8));
            }
            CP_COMMIT();
            cp_wait<0>();
        }
        __syncthreads();

        // ---- full-K-half mma: 3 n8-tiles x 2 passes ----
        float acc[3][4], accl[3][4];
#pragma unroll
        for (int j = 0; j < 3; j++)
#pragma unroll
            for (int q = 0; q < 4; q++) { acc[j][q] = 0.f; accl[j][q] = 0.f; }

#pragma unroll
        for (int kk = 0; kk < 16; kk++) {
            const int k16 = wk * 16 + kk;
            const uint32_t coloff = (k16 * 16 + lcol8) * 2;
            uint32_t a[4];
            ldmatrix_x4(a[0], a[1], a[2], a[3],
                        sb + SM_A + (wm * 16 + lrow) * (RSA * 2) + coloff);
            uint32_t bh[3][2], bl[3][2];
            {
                uint32_t r0, r1, r2, r3;
                ldmatrix_x4(r0, r1, r2, r3, sb + SM_BHI + lrow * (RSB * 2) + coloff);
                bh[0][0] = r0; bh[1][0] = r1; bh[0][1] = r2; bh[1][1] = r3;
                ldmatrix_x4(r0, r1, r2, r3, sb + SM_BLO + lrow * (RSB * 2) + coloff);
                bl[0][0] = r0; bl[1][0] = r1; bl[0][1] = r2; bl[1][1] = r3;
                const uint32_t a2 = (16 + (lane & 7)) * (RSB * 2) +
                                    (k16 * 16 + ((lane >> 3) & 1) * 8) * 2;
                ldmatrix_x2(bh[2][0], bh[2][1], sb + SM_BHI + a2);
                ldmatrix_x2(bl[2][0], bl[2][1], sb + SM_BLO + a2);
            }
#pragma unroll
            for (int nt = 0; nt < 3; nt++) {
                mma_f16(acc[nt], a, bh[nt]);
                mma_f16(accl[nt], a, bl[nt]);
            }
        }

        // ---- combine passes; intra-CTA k-reduce via smem ----
        float v[12];
#pragma unroll
        for (int nt = 0; nt < 3; nt++)
#pragma unroll
            for (int q = 0; q < 4; q++)
                v[nt * 4 + q] = fmaf(accl[nt][q], sc, acc[nt][q]);

        if (wk == 1) {
            float* rp = red + (wm * 32 + lane) * 13;
#pragma unroll
            for (int i = 0; i < 12; i++) rp[i] = v[i];
        }
        __syncthreads();

        // ---- gating: register-local z/r/n triplets ----
        if (wk == 0) {
            const float* rp = red + (wm * 32 + lane) * 13;
#pragma unroll
            for (int i = 0; i < 12; i++) v[i] += rp[i];
            __half* hdst = hbuf + (size_t)((t + 1) & 1) * (BB * HH);
#pragma unroll
            for (int rh = 0; rh < 2; rh++) {
#pragma unroll
                for (int ui = 0; ui < 2; ui++) {
                    const int q = rh * 2 + ui;
                    const int b = gr0 + rh * 8;
                    const int u = gu0 + ui;
                    float z = 1.f / (1.f + __expf(-(px[0][rh][ui] + v[0 + q])));
                    float r = 1.f / (1.f + __expf(-(px[1][rh][ui] + v[4 + q])));
                    float n = tanhf(px[2][rh][ui] + r * v[8 + q]);
                    float hn = fmaf(z, hold[rh][ui] - n, n);
                    hold[rh][ui] = hn;
                    y[((size_t)b * TT + t) * HH + u] = hn;
                    hdst[b * HH + u] = __float2half_rn(hn);
                }
            }
        }
        // next iteration's barrier (__syncthreads inside) protects SM_A reuse
    }
}

// ---------------- launch ----------------
extern "C" void kernel_launch(void* const* d_in, const int* in_sizes, int n_in,
                              void* d_out, int out_size) {
    const float* x  = (const float*)d_in[0];  // [B,T,I]
    const float* h0 = (const float*)d_in[1];  // [B,H]
    const float* Wx = (const float*)d_in[2];  // [3H,I]
    const float* bx = (const float*)d_in[3];  // [3H]
    const float* Wh = (const float*)d_in[4];  // [3H,H]
    float* out = (float*)d_out;

    float* xlin;
    __nv_bfloat16 *xhi, *xlo, *wxhi, *wxlo;
    __half *whh16, *whl16, *hbuf;
    cudaGetSymbolAddress((void**)&xlin, g_xlin);
    cudaGetSymbolAddress((void**)&xhi, g_xhi);
    cudaGetSymbolAddress((void**)&xlo, g_xlo);
    cudaGetSymbolAddress((void**)&wxhi, g_wxhi);
    cudaGetSymbolAddress((void**)&wxlo, g_wxlo);
    cudaGetSymbolAddress((void**)&whh16, g_whh16);
    cudaGetSymbolAddress((void**)&whl16, g_whl16);
    cudaGetSymbolAddress((void**)&hbuf, g_hb16);

    cudaFuncSetAttribute(gemm_xlin_mma, cudaFuncAttributeMaxDynamicSharedMemorySize,
                         2 * STG_B);
    cudaFuncSetAttribute(gru_persist_mma, cudaFuncAttributeMaxDynamicSharedMemorySize,
                         SMT);

    // launch order: ncu captures index 3 -> the recurrence
    reset_bar<<<1, 1>>>();                                              // 0
    {
        size_t tot = NX2 + NW2 + NH2 + NH0;
        split_all<<<(unsigned)((tot + 255) / 256), 256>>>(              // 1
            x, Wx, Wh, h0, xhi, xlo, wxhi, wxlo, whh16, whl16, hbuf);
    }
    gemm_xlin_mma<<<dim3(H3 / 64, (BB * TT) / 128), 256, 2 * STG_B>>>(  // 2
        xhi, xlo, wxhi, wxlo, bx, xlin);
    gru_persist_mma<<<NCTA, 256, SMT>>>(xlin, whh16, whl16, h0,         // 3
                                        hbuf, out);
    if (out_size >= (int)((size_t)BB * TT * HH + BB * HH)) {
        copy_hfinal<<<(BB * HH + 255) / 256, 256>>>(out, out + (size_t)BB * TT * HH,
                                                    BB * HH);           // 4
    }
}

// round 11
// speedup vs baseline: 5.2693x; 1.1357x over previous
#include <cuda_runtime.h>
#include <cuda_bf16.h>
#include <cuda_fp16.h>
#include <math.h>
#include <cstdint>

#define BB 128
#define TT 512
#define II 512
#define HH 512
#define H3 1536
#define KK 512
#define NCTA 128

// ---------------- scratch (device globals: allocation-free) ----------------
__device__ float g_xlin[(size_t)BB * TT * H3];            // [B,T,3H]
__device__ __half g_hb16[2][BB * HH];                     // h fp16 ping-pong
__device__ __nv_bfloat16 g_xhi[(size_t)BB * TT * II];     // x hi (bf16)
__device__ __nv_bfloat16 g_xlo[(size_t)BB * TT * II];     // x lo
__device__ __nv_bfloat16 g_wxhi[H3 * II];                 // Wx hi
__device__ __nv_bfloat16 g_wxlo[H3 * II];                 // Wx lo
__device__ __half g_whh16[H3 * KK];                       // Wh fp16, gate-permuted
__device__ int g_bar_count;

// ================= PTX helpers (baseline ISA only: sm_80+) =================
#define CP_ASYNC16(dst, src) \
    asm volatile("cp.async.cg.shared.global [%0], [%1], 16;" \
                 :: "r"(dst), "l"(src) : "memory")
#define CP_COMMIT() asm volatile("cp.async.commit_group;" ::: "memory")
template <int N>
__device__ __forceinline__ void cp_wait() {
    asm volatile("cp.async.wait_group %0;" :: "n"(N) : "memory");
}

__device__ __forceinline__ uint32_t smem_to_u32(const void* p) {
    uint32_t a;
    asm("{ .reg .u64 t; cvta.to.shared.u64 t, %1; cvt.u32.u64 %0, t; }"
        : "=r"(a) : "l"(p));
    return a;
}

__device__ __forceinline__ void ldmatrix_x4(uint32_t& r0, uint32_t& r1,
                                            uint32_t& r2, uint32_t& r3,
                                            uint32_t addr) {
    asm volatile("ldmatrix.sync.aligned.m8n8.x4.shared.b16 {%0,%1,%2,%3}, [%4];"
                 : "=r"(r0), "=r"(r1), "=r"(r2), "=r"(r3) : "r"(addr));
}

__device__ __forceinline__ void ldmatrix_x2(uint32_t& r0, uint32_t& r1,
                                            uint32_t addr) {
    asm volatile("ldmatrix.sync.aligned.m8n8.x2.shared.b16 {%0,%1}, [%2];"
                 : "=r"(r0), "=r"(r1) : "r"(addr));
}

__device__ __forceinline__ void mma_bf16(float* c, const uint32_t* a,
                                         const uint32_t* b) {
    asm volatile(
        "mma.sync.aligned.m16n8k16.row.col.f32.bf16.bf16.f32 "
        "{%0,%1,%2,%3}, {%4,%5,%6,%7}, {%8,%9}, {%0,%1,%2,%3};"
        : "+f"(c[0]), "+f"(c[1]), "+f"(c[2]), "+f"(c[3])
        : "r"(a[0]), "r"(a[1]), "r"(a[2]), "r"(a[3]), "r"(b[0]), "r"(b[1]));
}

__device__ __forceinline__ void mma_f16(float* c, const uint32_t* a,
                                        const uint32_t* b) {
    asm volatile(
        "mma.sync.aligned.m16n8k16.row.col.f32.f16.f16.f32 "
        "{%0,%1,%2,%3}, {%4,%5,%6,%7}, {%8,%9}, {%0,%1,%2,%3};"
        : "+f"(c[0]), "+f"(c[1]), "+f"(c[2]), "+f"(c[3])
        : "r"(a[0]), "r"(a[1]), "r"(a[2]), "r"(a[3]), "r"(b[0]), "r"(b[1]));
}

// ---------------- small helpers ----------------
__global__ void reset_bar() { g_bar_count = 0; }

__global__ void copy_hfinal(const float* __restrict__ y, float* __restrict__ dst,
                            int n) {
    int i = blockIdx.x * blockDim.x + threadIdx.x;
    if (i >= n) return;
    int b = i >> 9;
    int u = i & 511;
    dst[i] = y[((size_t)b * TT + (TT - 1)) * HH + u];
}

// combined split: x->bf16x2, Wx->bf16x2, Wh->fp16 gate-permuted, h0->fp16
#define NX2 ((size_t)BB * TT * II / 2)
#define NW2 ((size_t)H3 * II / 2)
#define NH2 ((size_t)H3 * KK / 2)
#define NH0 ((size_t)BB * HH / 2)
__global__ void split_all(const float* __restrict__ x,
                          const float* __restrict__ wx,
                          const float* __restrict__ wh,
                          const float* __restrict__ h0,
                          __nv_bfloat16* __restrict__ xhi,
                          __nv_bfloat16* __restrict__ xlo,
                          __nv_bfloat16* __restrict__ wxhi,
                          __nv_bfloat16* __restrict__ wxlo,
                          __half* __restrict__ whh16,
                          __half* __restrict__ hb0) {
    size_t i = (size_t)blockIdx.x * blockDim.x + threadIdx.x;
    if (i < NX2 + NW2) {
        const float* src;
        __nv_bfloat16 *hi, *lo;
        size_t j;
        if (i < NX2) { src = x; hi = xhi; lo = xlo; j = i; }
        else { src = wx; hi = wxhi; lo = wxlo; j = i - NX2; }
        float2 v = ((const float2*)src)[j];
        __nv_bfloat16 h0b = __float2bfloat16(v.x);
        __nv_bfloat16 h1b = __float2bfloat16(v.y);
        ((__nv_bfloat162*)hi)[j] = __nv_bfloat162(h0b, h1b);
        ((__nv_bfloat162*)lo)[j] =
            __nv_bfloat162(__float2bfloat16(v.x - __bfloat162float(h0b)),
                           __float2bfloat16(v.y - __bfloat162float(h1b)));
    } else if (i < NX2 + NW2 + NH2) {
        size_t j = i - NX2 - NW2;
        int g = (int)(j >> 8);            // Wh row 0..1535
        int k2 = (int)(j & 255);          // half2 col index
        int gate = g >> 9;
        int u = g & 511;
        int prow = (u >> 3) * 24 + gate * 8 + (u & 7);   // gate-permuted row
        float2 v = ((const float2*)wh)[j];
        ((__half2*)whh16)[(size_t)prow * 256 + k2] =
            __halves2half2(__float2half_rn(v.x), __float2half_rn(v.y));
    } else if (i < NX2 + NW2 + NH2 + NH0) {
        size_t j = i - NX2 - NW2 - NH2;
        float2 v = ((const float2*)h0)[j];
        ((__half2*)hb0)[j] = __halves2half2(__float2half_rn(v.x),
                                            __float2half_rn(v.y));
    }
}

// ---------------- Phase 1: bf16-split GEMM, 3-stage cp.async pipeline -----
#define SA 40
#define A_T (128 * SA * 2)
#define B_T (64 * SA * 2)
#define STG_B (2 * A_T + 2 * B_T)           // 30720 per stage
#define O_AH 0
#define O_AL A_T
#define O_BH (2 * A_T)
#define O_BL (2 * A_T + B_T)

__global__ void __launch_bounds__(256, 2) gemm_xlin_mma(
    const __nv_bfloat16* __restrict__ Ahi, const __nv_bfloat16* __restrict__ Alo,
    const __nv_bfloat16* __restrict__ Bhi, const __nv_bfloat16* __restrict__ Blo,
    const float* __restrict__ bias, float* __restrict__ C) {
    extern __shared__ char smem[];
    const uint32_t sb = smem_to_u32(smem);

    const int tid = threadIdx.x;
    const int wid = tid >> 5;
    const int lane = tid & 31;
    const int wrow = wid >> 2;
    const int wcol = wid & 3;
    const int n0 = blockIdx.x * 64;
    const int m0 = blockIdx.y * 128;

    const __nv_bfloat16* ga_h = Ahi + (size_t)m0 * KK;
    const __nv_bfloat16* ga_l = Alo + (size_t)m0 * KK;
    const __nv_bfloat16* gb_h = Bhi + (size_t)n0 * KK;
    const __nv_bfloat16* gb_l = Blo + (size_t)n0 * KK;

    const int ra = tid >> 1;
    const int ga2 = (tid & 1) * 2;
    const int rb = tid >> 2;
    const int gb1 = tid & 3;

    auto stage = [&](int kc, int buf) {
        const uint32_t d = sb + buf * STG_B;
        const __nv_bfloat16* sa_h = ga_h + (size_t)ra * KK + kc * 32;
        const __nv_bfloat16* sa_l = ga_l + (size_t)ra * KK + kc * 32;
        CP_ASYNC16(d + O_AH + ra * 80 + ga2 * 16, (const void*)(sa_h + ga2 * 8));
        CP_ASYNC16(d + O_AH + ra * 80 + (ga2 + 1) * 16, (const void*)(sa_h + (ga2 + 1) * 8));
        CP_ASYNC16(d + O_AL + ra * 80 + ga2 * 16, (const void*)(sa_l + ga2 * 8));
        CP_ASYNC16(d + O_AL + ra * 80 + (ga2 + 1) * 16, (const void*)(sa_l + (ga2 + 1) * 8));
        const __nv_bfloat16* sb_h = gb_h + (size_t)rb * KK + kc * 32;
        const __nv_bfloat16* sb_l = gb_l + (size_t)rb * KK + kc * 32;
        CP_ASYNC16(d + O_BH + rb * 80 + gb1 * 16, (const void*)(sb_h + gb1 * 8));
        CP_ASYNC16(d + O_BL + rb * 80 + gb1 * 16, (const void*)(sb_l + gb1 * 8));
        CP_COMMIT();
    };

    float acc[4][2][4];
#pragma unroll
    for (int i = 0; i < 4; i++)
#pragma unroll
        for (int j = 0; j < 2; j++)
#pragma unroll
            for (int q = 0; q < 4; q++) acc[i][j][q] = 0.f;

    const int lrow = lane & 15;
    const int lcol8 = (lane >> 4) * 8;

    const int NCHUNK = KK / 32;             // 16
    stage(0, 0);
    stage(1, 1);

    for (int kc = 0; kc < NCHUNK; kc++) {
        if (kc + 1 < NCHUNK) { cp_wait<1>(); } else { cp_wait<0>(); }
        __syncthreads();                    // chunk kc visible; compute(kc-1) done
        if (kc + 2 < NCHUNK) stage(kc + 2, (kc + 2) % 3);

        const uint32_t bb = sb + (kc % 3) * STG_B;
#pragma unroll
        for (int ks = 0; ks < 2; ks++) {
            const uint32_t coloff = (ks * 16 + lcol8) * 2;
            uint32_t bh[2][2], bl[2][2];
            {
                const uint32_t brow = (wcol * 16 + lrow) * 80;
                uint32_t r0, r1, r2, r3;
                ldmatrix_x4(r0, r1, r2, r3, bb + O_BH + brow + coloff);
                bh[0][0] = r0; bh[1][0] = r1; bh[0][1] = r2; bh[1][1] = r3;
                ldmatrix_x4(r0, r1, r2, r3, bb + O_BL + brow + coloff);
                bl[0][0] = r0; bl[1][0] = r1; bl[0][1] = r2; bl[1][1] = r3;
            }
#pragma unroll
            for (int mt = 0; mt < 4; mt++) {
                const uint32_t arow = (wrow * 64 + mt * 16 + lrow) * 80;
                uint32_t ah[4], al[4];
                ldmatrix_x4(ah[0], ah[1], ah[2], ah[3], bb + O_AH + arow + coloff);
                ldmatrix_x4(al[0], al[1], al[2], al[3], bb + O_AL + arow + coloff);
#pragma unroll
                for (int nt = 0; nt < 2; nt++) {
                    mma_bf16(acc[mt][nt], ah, bh[nt]);
                    mma_bf16(acc[mt][nt], ah, bl[nt]);
                    mma_bf16(acc[mt][nt], al, bh[nt]);
                }
            }
        }
    }

    const int erow = m0 + wrow * 64 + (lane >> 2);
    const int ecol0 = n0 + wcol * 16 + (lane & 3) * 2;
#pragma unroll
    for (int mt = 0; mt < 4; mt++) {
#pragma unroll
        for (int nt = 0; nt < 2; nt++) {
            const int col = ecol0 + nt * 8;
            const float b0 = bias[col], b1 = bias[col + 1];
            const int r0 = erow + mt * 16;
            *(float2*)(C + (size_t)r0 * H3 + col) =
                make_float2(acc[mt][nt][0] + b0, acc[mt][nt][1] + b1);
            *(float2*)(C + (size_t)(r0 + 8) * H3 + col) =
                make_float2(acc[mt][nt][2] + b0, acc[mt][nt][3] + b1);
        }
    }
}

// ---------------- grid-wide barrier: monotonic RED + poll ----------------
__device__ __forceinline__ void grid_barrier(int phase) {
    __syncthreads();
    if (threadIdx.x == 0) {
        __threadfence();                       // release
        atomicAdd(&g_bar_count, 1);
        const int target = NCTA * phase;
        while (*((volatile int*)&g_bar_count) < target) { }
        __threadfence();                       // acquire
    }
    __syncthreads();
}

// ---------------- Phase 2: fused recurrence, single fp16 pass -------------
// 128 CTAs = 64 unit-groups x 2 batch-halves; CTA tile 64b x 24n x 512k.
// K split by PARITY across warp groups (wk): k16 = 2j + wk, so both groups
// start in A-chunk 0 -> chunked cp.async staging overlaps with mma.
// Gating register-local (gate-permuted Wh rows); h ping-pong fp16.
#define RSA 520
#define RSB 520
#define SM_A 0
#define A_SZ (64 * RSA * 2)             // 66560
#define SM_BHI A_SZ
#define B_SZ (24 * RSB * 2)             // 24960
#define SM_RED (SM_BHI + B_SZ)
#define SMT (SM_RED + 4 * 32 * 13 * 4)  // 98176

__global__ void __launch_bounds__(256, 1) gru_persist_mma(
    const float* __restrict__ xlin,
    const __half* __restrict__ whh16,
    const float* __restrict__ h0,
    __half* __restrict__ hbuf,          // 2 x BB*HH fp16 ping-pong
    float* __restrict__ y) {
    extern __shared__ char smh[];
    const uint32_t sb = smem_to_u32(smh);
    float* red = (float*)(smh + SM_RED);

    const int tid = threadIdx.x;
    const int lane = tid & 31;
    const int wid = tid >> 5;
    const int wm = wid & 3;             // m16-tile 0..3
    const int wk = wid >> 2;            // k-parity 0..1
    const int cta = blockIdx.x;
    const int ug = cta >> 1;            // unit group 0..63
    const int mh = cta & 1;             // batch half
    const int b0 = mh * 64;
    const int lrow = lane & 15;
    const int lcol8 = (lane >> 4) * 8;

    const int gr0 = b0 + wm * 16 + (lane >> 2);
    const int gu0 = ug * 8 + (lane & 3) * 2;

    float hold[2][2];
    if (wk == 0) {
#pragma unroll
        for (int rh = 0; rh < 2; rh++)
#pragma unroll
            for (int ui = 0; ui < 2; ui++)
                hold[rh][ui] = h0[(gr0 + rh * 8) * HH + gu0 + ui];
    }

    // ---- stage resident permuted Wh tile: rows [ug*24, +24) x 512 k ----
    {
#pragma unroll
        for (int i = 0; i < 6; i++) {
            int c = tid + i * 256;            // 0..1535
            int row = c >> 6;                 // 0..23
            int seg = c & 63;
            CP_ASYNC16(sb + SM_BHI + (row * RSB + seg * 8) * 2,
                       (const void*)(whh16 + (size_t)(ug * 24 + row) * KK + seg * 8));
        }
        CP_COMMIT();
        cp_wait<0>();
    }
    __syncthreads();

    // one k16-step of mma on staged data
    auto do_k = [&](int j, float acc[3][4]) {
        const int k16 = 2 * j + wk;
        const uint32_t coloff = (k16 * 16 + lcol8) * 2;
        uint32_t a[4];
        ldmatrix_x4(a[0], a[1], a[2], a[3],
                    sb + SM_A + (wm * 16 + lrow) * (RSA * 2) + coloff);
        uint32_t bh[3][2];
        {
            uint32_t r0, r1, r2, r3;
            ldmatrix_x4(r0, r1, r2, r3, sb + SM_BHI + lrow * (RSB * 2) + coloff);
            bh[0][0] = r0; bh[1][0] = r1; bh[0][1] = r2; bh[1][1] = r3;
            const uint32_t a2 = (16 + (lane & 7)) * (RSB * 2) +
                                (k16 * 16 + ((lane >> 3) & 1) * 8) * 2;
            ldmatrix_x2(bh[2][0], bh[2][1], sb + SM_BHI + a2);
        }
#pragma unroll
        for (int nt = 0; nt < 3; nt++) mma_f16(acc[nt], a, bh[nt]);
    };

    for (int t = 0; t < TT; t++) {
        // ---- prefetch xlin gate operands BEFORE barrier (constant data) ----
        float px[3][2][2];
        if (wk == 0) {
            const float* xlb0 = xlin + (size_t)t * H3;
#pragma unroll
            for (int rh = 0; rh < 2; rh++) {
                const float* xl = xlb0 + (size_t)(gr0 + rh * 8) * (TT * H3);
#pragma unroll
                for (int ui = 0; ui < 2; ui++) {
                    px[0][rh][ui] = xl[gu0 + ui];
                    px[1][rh][ui] = xl[gu0 + ui + 512];
                    px[2][rh][ui] = xl[gu0 + ui + 1024];
                }
            }
        }

        grid_barrier(t + 1);            // h(t-1) fp16 visible everywhere

        // ---- stage A = h fp16 [64b x 512k] in 2 chunks (k halves) ----
        const __half* hsrc = hbuf + (size_t)(t & 1) * (BB * HH);
#pragma unroll
        for (int ch = 0; ch < 2; ch++) {
#pragma unroll
            for (int i = 0; i < 8; i++) {
                int c = tid + i * 256;        // 0..2047
                int row = c >> 5;             // 0..63
                int seg = ch * 32 + (c & 31);
                CP_ASYNC16(sb + SM_A + (row * RSA + seg * 8) * 2,
                           (const void*)(hsrc + (size_t)(b0 + row) * HH + seg * 8));
            }
            CP_COMMIT();
        }

        float acc[3][4];
#pragma unroll
        for (int j = 0; j < 3; j++)
#pragma unroll
            for (int q = 0; q < 4; q++) acc[j][q] = 0.f;

        cp_wait<1>();                   // chunk 0 (k 0..255) ready
        __syncthreads();
#pragma unroll
        for (int j = 0; j < 8; j++) do_k(j, acc);      // k16 0..15 (parity wk)

        cp_wait<0>();                   // chunk 1 ready
        __syncthreads();
#pragma unroll
        for (int j = 8; j < 16; j++) do_k(j, acc);     // k16 16..31

        // ---- intra-CTA k-parity reduce via smem ----
        float v[12];
#pragma unroll
        for (int nt = 0; nt < 3; nt++)
#pragma unroll
            for (int q = 0; q < 4; q++) v[nt * 4 + q] = acc[nt][q];

        if (wk == 1) {
            float* rp = red + (wm * 32 + lane) * 13;
#pragma unroll
            for (int i = 0; i < 12; i++) rp[i] = v[i];
        }
        __syncthreads();

        // ---- gating: register-local z/r/n triplets ----
        if (wk == 0) {
            const float* rp = red + (wm * 32 + lane) * 13;
#pragma unroll
            for (int i = 0; i < 12; i++) v[i] += rp[i];
            __half* hdst = hbuf + (size_t)((t + 1) & 1) * (BB * HH);
#pragma unroll
            for (int rh = 0; rh < 2; rh++) {
#pragma unroll
                for (int ui = 0; ui < 2; ui++) {
                    const int q = rh * 2 + ui;
                    const int b = gr0 + rh * 8;
                    const int u = gu0 + ui;
                    float z = 1.f / (1.f + __expf(-(px[0][rh][ui] + v[0 + q])));
                    float r = 1.f / (1.f + __expf(-(px[1][rh][ui] + v[4 + q])));
                    float n = tanhf(px[2][rh][ui] + r * v[8 + q]);
                    float hn = fmaf(z, hold[rh][ui] - n, n);
                    hold[rh][ui] = hn;
                    y[((size_t)b * TT + t) * HH + u] = hn;
                    hdst[b * HH + u] = __float2half_rn(hn);
                }
            }
        }
        // next iteration's barrier syncthreads protects SM_A reuse
    }
}

// ---------------- launch ----------------
extern "C" void kernel_launch(void* const* d_in, const int* in_sizes, int n_in,
                              void* d_out, int out_size) {
    const float* x  = (const float*)d_in[0];  // [B,T,I]
    const float* h0 = (const float*)d_in[1];  // [B,H]
    const float* Wx = (const float*)d_in[2];  // [3H,I]
    const float* bx = (const float*)d_in[3];  // [3H]
    const float* Wh = (const float*)d_in[4];  // [3H,H]
    float* out = (float*)d_out;

    float* xlin;
    __nv_bfloat16 *xhi, *xlo, *wxhi, *wxlo;
    __half *whh16, *hbuf;
    cudaGetSymbolAddress((void**)&xlin, g_xlin);
    cudaGetSymbolAddress((void**)&xhi, g_xhi);
    cudaGetSymbolAddress((void**)&xlo, g_xlo);
    cudaGetSymbolAddress((void**)&wxhi, g_wxhi);
    cudaGetSymbolAddress((void**)&wxlo, g_wxlo);
    cudaGetSymbolAddress((void**)&whh16, g_whh16);
    cudaGetSymbolAddress((void**)&hbuf, g_hb16);

    cudaFuncSetAttribute(gemm_xlin_mma, cudaFuncAttributeMaxDynamicSharedMemorySize,
                         3 * STG_B);
    cudaFuncSetAttribute(gru_persist_mma, cudaFuncAttributeMaxDynamicSharedMemorySize,
                         SMT);

    // launch order: ncu captures index 3 -> the recurrence
    reset_bar<<<1, 1>>>();                                              // 0
    {
        size_t tot = NX2 + NW2 + NH2 + NH0;
        split_all<<<(unsigned)((tot + 255) / 256), 256>>>(              // 1
            x, Wx, Wh, h0, xhi, xlo, wxhi, wxlo, whh16, hbuf);
    }
    gemm_xlin_mma<<<dim3(H3 / 64, (BB * TT) / 128), 256, 3 * STG_B>>>(  // 2
        xhi, xlo, wxhi, wxlo, bx, xlin);
    gru_persist_mma<<<NCTA, 256, SMT>>>(xlin, whh16, h0, hbuf, out);    // 3
    if (out_size >= (int)((size_t)BB * TT * HH + BB * HH)) {
        copy_hfinal<<<(BB * HH + 255) / 256, 256>>>(out, out + (size_t)BB * TT * HH,
                                                    BB * HH);           // 4
    }
}